// round 1
// baseline (speedup 1.0000x reference)
#include <cuda_runtime.h>
#include <cstddef>

#define BATCH 4
#define SEQ   2048
#define EMB   1024
#define NH    16
#define HD    64

// Scratch: projected q,k,v and attention output. __device__ globals (no allocs).
__device__ float g_q[(size_t)BATCH * SEQ * EMB];
__device__ float g_k[(size_t)BATCH * SEQ * EMB];
__device__ float g_v[(size_t)BATCH * SEQ * EMB];
__device__ float g_a[(size_t)BATCH * SEQ * EMB];

// ---------------------------------------------------------------------------
// GEMM:  C[M,N] = A[M,K] @ W[N,K]^T + bias[N]
// 128x128 block tile, BK=16, 256 threads, 8x8 per-thread microtile.
// A and W are both K-major (row-major with K contiguous) -> "NT" layout.
// ---------------------------------------------------------------------------
__global__ __launch_bounds__(256)
void gemm_nt_bias(const float* __restrict__ A, const float* __restrict__ W,
                  const float* __restrict__ bias, float* __restrict__ C,
                  int M, int N, int K)
{
    __shared__ float As[16][128];
    __shared__ float Ws[16][128];

    const int tid  = threadIdx.x;
    const int tcol = tid & 15;      // 0..15  -> cols
    const int trow = tid >> 4;      // 0..15  -> rows
    const int bm = blockIdx.y * 128;
    const int bn = blockIdx.x * 128;

    const float* Ap = A + (size_t)bm * K;
    const float* Wp = W + (size_t)bn * K;

    float acc[8][8];
    #pragma unroll
    for (int i = 0; i < 8; i++)
        #pragma unroll
        for (int j = 0; j < 8; j++) acc[i][j] = 0.f;

    for (int k0 = 0; k0 < K; k0 += 16) {
        // Load 128x16 tiles of A and W, transposed into smem [k][m]/[k][n].
        #pragma unroll
        for (int it = 0; it < 2; it++) {
            int idx = tid + it * 256;         // 0..511 float4 slots
            int r   = idx >> 2;               // 0..127
            int c4  = (idx & 3) << 2;         // 0,4,8,12
            float4 va = *(const float4*)(Ap + (size_t)r * K + k0 + c4);
            As[c4 + 0][r] = va.x; As[c4 + 1][r] = va.y;
            As[c4 + 2][r] = va.z; As[c4 + 3][r] = va.w;
            float4 vw = *(const float4*)(Wp + (size_t)r * K + k0 + c4);
            Ws[c4 + 0][r] = vw.x; Ws[c4 + 1][r] = vw.y;
            Ws[c4 + 2][r] = vw.z; Ws[c4 + 3][r] = vw.w;
        }
        __syncthreads();

        #pragma unroll
        for (int kk = 0; kk < 16; kk++) {
            float a[8], b[8];
            *(float4*)&a[0] = *(const float4*)&As[kk][trow * 8];
            *(float4*)&a[4] = *(const float4*)&As[kk][trow * 8 + 4];
            *(float4*)&b[0] = *(const float4*)&Ws[kk][tcol * 8];
            *(float4*)&b[4] = *(const float4*)&Ws[kk][tcol * 8 + 4];
            #pragma unroll
            for (int i = 0; i < 8; i++)
                #pragma unroll
                for (int j = 0; j < 8; j++)
                    acc[i][j] += a[i] * b[j];
        }
        __syncthreads();
    }

    #pragma unroll
    for (int i = 0; i < 8; i++) {
        size_t row = (size_t)(bm + trow * 8 + i);
        #pragma unroll
        for (int j4 = 0; j4 < 8; j4 += 4) {
            int col = bn + tcol * 8 + j4;
            float4 o;
            o.x = acc[i][j4 + 0] + bias[col + 0];
            o.y = acc[i][j4 + 1] + bias[col + 1];
            o.z = acc[i][j4 + 2] + bias[col + 2];
            o.w = acc[i][j4 + 3] + bias[col + 3];
            *(float4*)(C + row * N + col) = o;
        }
    }
}

// ---------------------------------------------------------------------------
// Flash attention (causal), fp32. One block = 64 queries of one (b,h).
// Tiles of 64 keys. Online softmax. D = 64.
// grid = (SEQ/64, NH, BATCH), 256 threads (16x16 microtile layout, 4x4 each).
// ---------------------------------------------------------------------------
#define NEG_BIG (-1e30f)

__global__ __launch_bounds__(256)
void attn_kernel(const float* __restrict__ Q, const float* __restrict__ K,
                 const float* __restrict__ V, float* __restrict__ O)
{
    extern __shared__ float sm[];
    float* Qs = sm;                  // [64][65]  (query x d, scaled)
    float* Ks = Qs + 64 * 65;        // [64][65]  (key x d)
    float* Vs = Ks + 64 * 65;        // [64][65]  (key x d)
    float* Ps = Vs + 64 * 65;        // [64][65]  (key x query)  -- P transposed
    float* Ms = Ps + 64 * 65;        // [64] running max
    float* Ls = Ms + 64;             // [64] running sum

    const int tid = threadIdx.x;
    const int tx  = tid & 15;        // key/dcol group
    const int ty  = tid >> 4;        // query-row group
    const int qb  = blockIdx.x * 64;
    const int h   = blockIdx.y;
    const int b   = blockIdx.z;
    const size_t base = ((size_t)b * SEQ) * EMB + (size_t)h * HD;

    // Load Q tile, pre-scaled by 1/sqrt(D) = 0.125
    #pragma unroll
    for (int t = 0; t < 4; t++) {
        int idx = tid + t * 256;           // 0..1023 float4 slots
        int r   = idx >> 4;                // 0..63
        int c   = (idx & 15) << 2;         // 0..60
        float4 v = *(const float4*)(Q + base + (size_t)(qb + r) * EMB + c);
        Qs[r * 65 + c + 0] = v.x * 0.125f;
        Qs[r * 65 + c + 1] = v.y * 0.125f;
        Qs[r * 65 + c + 2] = v.z * 0.125f;
        Qs[r * 65 + c + 3] = v.w * 0.125f;
    }
    if (tid < 64) { Ms[tid] = NEG_BIG; Ls[tid] = 0.f; }

    float acc[4][4];
    #pragma unroll
    for (int i = 0; i < 4; i++)
        #pragma unroll
        for (int j = 0; j < 4; j++) acc[i][j] = 0.f;

    const int nk = blockIdx.x + 1;   // causal: only key tiles with kbase <= qb
    for (int kb = 0; kb < nk; kb++) {
        const int kbase = kb * 64;
        __syncthreads();             // prior PV reads of Ks/Vs/Ps done

        // Load K and V tiles (natural [key][d] layout, pad 65)
        #pragma unroll
        for (int t = 0; t < 4; t++) {
            int idx = tid + t * 256;
            int r   = idx >> 4;
            int c   = (idx & 15) << 2;
            float4 vk = *(const float4*)(K + base + (size_t)(kbase + r) * EMB + c);
            Ks[r * 65 + c + 0] = vk.x; Ks[r * 65 + c + 1] = vk.y;
            Ks[r * 65 + c + 2] = vk.z; Ks[r * 65 + c + 3] = vk.w;
            float4 vv = *(const float4*)(V + base + (size_t)(kbase + r) * EMB + c);
            Vs[r * 65 + c + 0] = vv.x; Vs[r * 65 + c + 1] = vv.y;
            Vs[r * 65 + c + 2] = vv.z; Vs[r * 65 + c + 3] = vv.w;
        }
        __syncthreads();

        // S = Qs . Ks^T  (4x4 per thread)
        float s[4][4];
        #pragma unroll
        for (int i = 0; i < 4; i++)
            #pragma unroll
            for (int j = 0; j < 4; j++) s[i][j] = 0.f;

        #pragma unroll 16
        for (int d = 0; d < 64; d++) {
            float a0 = Qs[(ty * 4 + 0) * 65 + d];
            float a1 = Qs[(ty * 4 + 1) * 65 + d];
            float a2 = Qs[(ty * 4 + 2) * 65 + d];
            float a3 = Qs[(ty * 4 + 3) * 65 + d];
            float b0 = Ks[(tx * 4 + 0) * 65 + d];
            float b1 = Ks[(tx * 4 + 1) * 65 + d];
            float b2 = Ks[(tx * 4 + 2) * 65 + d];
            float b3 = Ks[(tx * 4 + 3) * 65 + d];
            s[0][0] += a0 * b0; s[0][1] += a0 * b1; s[0][2] += a0 * b2; s[0][3] += a0 * b3;
            s[1][0] += a1 * b0; s[1][1] += a1 * b1; s[1][2] += a1 * b2; s[1][3] += a1 * b3;
            s[2][0] += a2 * b0; s[2][1] += a2 * b1; s[2][2] += a2 * b2; s[2][3] += a2 * b3;
            s[3][0] += a3 * b0; s[3][1] += a3 * b1; s[3][2] += a3 * b2; s[3][3] += a3 * b3;
        }

        // Causal mask (only diagonal tile needs it)
        if (kb == nk - 1) {
            #pragma unroll
            for (int i = 0; i < 4; i++) {
                int qrow = qb + ty * 4 + i;
                #pragma unroll
                for (int j = 0; j < 4; j++) {
                    int kcol = kbase + tx * 4 + j;
                    if (kcol > qrow) s[i][j] = NEG_BIG;
                }
            }
        }

        // Online softmax per row (16 lanes of same ty share a row group)
        #pragma unroll
        for (int i = 0; i < 4; i++) {
            const int row = ty * 4 + i;
            float mloc = fmaxf(fmaxf(s[i][0], s[i][1]), fmaxf(s[i][2], s[i][3]));
            #pragma unroll
            for (int off = 8; off; off >>= 1)
                mloc = fmaxf(mloc, __shfl_xor_sync(0xffffffffu, mloc, off));
            float mold = Ms[row];
            float mnew = fmaxf(mold, mloc);
            float corr = __expf(mold - mnew);
            float psum = 0.f;
            #pragma unroll
            for (int j = 0; j < 4; j++) {
                float p = __expf(s[i][j] - mnew);
                Ps[(tx * 4 + j) * 65 + row] = p;
                psum += p;
                acc[i][j] *= corr;   // rescale O accumulator (cols here are d)
            }
            #pragma unroll
            for (int off = 8; off; off >>= 1)
                psum += __shfl_xor_sync(0xffffffffu, psum, off);
            __syncwarp();
            if (tx == 0) { Ms[row] = mnew; Ls[row] = Ls[row] * corr + psum; }
        }
        __syncthreads();   // Ps complete

        // O += P . V   (acc cols = head dim)
        #pragma unroll 16
        for (int c = 0; c < 64; c++) {
            float p0 = Ps[c * 65 + ty * 4 + 0];
            float p1 = Ps[c * 65 + ty * 4 + 1];
            float p2 = Ps[c * 65 + ty * 4 + 2];
            float p3 = Ps[c * 65 + ty * 4 + 3];
            float v0 = Vs[c * 65 + tx * 4 + 0];
            float v1 = Vs[c * 65 + tx * 4 + 1];
            float v2 = Vs[c * 65 + tx * 4 + 2];
            float v3 = Vs[c * 65 + tx * 4 + 3];
            acc[0][0] += p0 * v0; acc[0][1] += p0 * v1; acc[0][2] += p0 * v2; acc[0][3] += p0 * v3;
            acc[1][0] += p1 * v0; acc[1][1] += p1 * v1; acc[1][2] += p1 * v2; acc[1][3] += p1 * v3;
            acc[2][0] += p2 * v0; acc[2][1] += p2 * v1; acc[2][2] += p2 * v2; acc[2][3] += p2 * v3;
            acc[3][0] += p3 * v0; acc[3][1] += p3 * v1; acc[3][2] += p3 * v2; acc[3][3] += p3 * v3;
        }
    }
    __syncthreads();

    // Normalize and write out
    #pragma unroll
    for (int i = 0; i < 4; i++) {
        int row = ty * 4 + i;
        float inv = 1.f / Ls[row];
        float4 o;
        o.x = acc[i][0] * inv; o.y = acc[i][1] * inv;
        o.z = acc[i][2] * inv; o.w = acc[i][3] * inv;
        *(float4*)(O + base + (size_t)(qb + row) * EMB + tx * 4) = o;
    }
}

// ---------------------------------------------------------------------------
extern "C" void kernel_launch(void* const* d_in, const int* in_sizes, int n_in,
                              void* d_out, int out_size)
{
    const float* query = (const float*)d_in[0];
    const float* key   = (const float*)d_in[1];
    const float* value = (const float*)d_in[2];
    // d_in[3] = attn_mask (tril) -> replaced by causal predicate in-kernel
    const float* Wq = (const float*)d_in[4];  const float* bq = (const float*)d_in[5];
    const float* Wk = (const float*)d_in[6];  const float* bk = (const float*)d_in[7];
    const float* Wv = (const float*)d_in[8];  const float* bv = (const float*)d_in[9];
    const float* Wo = (const float*)d_in[10]; const float* bo = (const float*)d_in[11];
    float* out = (float*)d_out;

    float *qp, *kp, *vp, *ap;
    cudaGetSymbolAddress((void**)&qp, g_q);
    cudaGetSymbolAddress((void**)&kp, g_k);
    cudaGetSymbolAddress((void**)&vp, g_v);
    cudaGetSymbolAddress((void**)&ap, g_a);

    const int M = BATCH * SEQ;             // 8192
    dim3 ggrid(EMB / 128, M / 128);        // (8, 64)

    gemm_nt_bias<<<ggrid, 256>>>(query, Wq, bq, qp, M, EMB, EMB);
    gemm_nt_bias<<<ggrid, 256>>>(key,   Wk, bk, kp, M, EMB, EMB);
    gemm_nt_bias<<<ggrid, 256>>>(value, Wv, bv, vp, M, EMB, EMB);

    int smem = (4 * 64 * 65 + 128) * (int)sizeof(float);   // 67072 B
    cudaFuncSetAttribute(attn_kernel, cudaFuncAttributeMaxDynamicSharedMemorySize, smem);
    attn_kernel<<<dim3(SEQ / 64, NH, BATCH), 256, smem>>>(qp, kp, vp, ap);

    gemm_nt_bias<<<ggrid, 256>>>(ap, Wo, bo, out, M, EMB, EMB);
}

// round 3
// speedup vs baseline: 1.6483x; 1.6483x over previous
#include <cuda_runtime.h>
#include <cuda_bf16.h>
#include <cstdint>
#include <cstddef>

#define BATCH 4
#define SEQ   2048
#define EMB   1024
#define NH    16
#define HD    64
#define MTOT  (BATCH * SEQ)        /* 8192 */
#define KSPLIT (3 * EMB)           /* 3072 */
#define BK    32
#define NITER (KSPLIT / BK)        /* 96 */

// ---------------- scratch (__device__ globals; no allocs) -------------------
__device__ __align__(1024) float g_q[(size_t)MTOT * EMB];
__device__ __align__(1024) float g_k[(size_t)MTOT * EMB];
__device__ __align__(1024) float g_v[(size_t)MTOT * EMB];
__device__ __align__(1024) float g_a[(size_t)MTOT * EMB];
__device__ __align__(1024) __nv_bfloat16 g_a3[(size_t)MTOT * KSPLIT];   // 48MB
__device__ __align__(1024) __nv_bfloat16 g_w3[4][(size_t)EMB * KSPLIT]; // 4x6MB

// ---------------- PTX helpers (baseline ISA only: sm_80-era ops) ------------
__device__ __forceinline__ uint32_t smem_u32(const void* p) {
    uint32_t a;
    asm("{ .reg .u64 t; cvta.to.shared.u64 t, %1; cvt.u32.u64 %0, t; }" : "=r"(a) : "l"(p));
    return a;
}
#define CP_ASYNC16(dst, src) \
    asm volatile("cp.async.cg.shared.global [%0], [%1], 16;" :: "r"(dst), "l"(src) : "memory")
#define CP_COMMIT() asm volatile("cp.async.commit_group;" ::: "memory")
#define CP_WAIT2()  asm volatile("cp.async.wait_group 2;" ::: "memory")

__device__ __forceinline__ void ldsm4(uint32_t (&r)[4], uint32_t addr) {
    asm volatile("ldmatrix.sync.aligned.m8n8.x4.shared.b16 {%0,%1,%2,%3}, [%4];"
                 : "=r"(r[0]), "=r"(r[1]), "=r"(r[2]), "=r"(r[3]) : "r"(addr));
}
__device__ __forceinline__ void mma16816(float (&d)[4], const uint32_t (&a)[4],
                                         const uint32_t (&b)[2]) {
    asm volatile(
        "mma.sync.aligned.m16n8k16.row.col.f32.bf16.bf16.f32 "
        "{%0,%1,%2,%3}, {%4,%5,%6,%7}, {%8,%9}, {%0,%1,%2,%3};"
        : "+f"(d[0]), "+f"(d[1]), "+f"(d[2]), "+f"(d[3])
        : "r"(a[0]), "r"(a[1]), "r"(a[2]), "r"(a[3]), "r"(b[0]), "r"(b[1]));
}

// ---------------------------------------------------------------------------
// fp32 -> (hi,lo) bf16 split, written as 3 K-blocks.
//   A mode: [hi | lo | hi ]  (off_lo=1024, off_hi2=2048)
//   W mode: [hi | hi | lo ]  (off_lo=2048, off_hi2=1024)
// ---------------------------------------------------------------------------
__device__ __forceinline__ uint32_t pk2(__nv_bfloat16 a, __nv_bfloat16 b) {
    __nv_bfloat162 t = __halves2bfloat162(a, b);
    return *reinterpret_cast<uint32_t*>(&t);
}
__global__ __launch_bounds__(256)
void split3(const float* __restrict__ X, __nv_bfloat16* __restrict__ Y,
            int off_lo, int off_hi2)
{
    size_t idx = (size_t)blockIdx.x * 256 + threadIdx.x;
    size_t row = idx >> 8;
    int    c   = (int)(idx & 255) << 2;
    float4 x = ((const float4*)X)[idx];
    __nv_bfloat16 h0 = __float2bfloat16(x.x), h1 = __float2bfloat16(x.y);
    __nv_bfloat16 h2 = __float2bfloat16(x.z), h3 = __float2bfloat16(x.w);
    __nv_bfloat16 l0 = __float2bfloat16(x.x - __bfloat162float(h0));
    __nv_bfloat16 l1 = __float2bfloat16(x.y - __bfloat162float(h1));
    __nv_bfloat16 l2 = __float2bfloat16(x.z - __bfloat162float(h2));
    __nv_bfloat16 l3 = __float2bfloat16(x.w - __bfloat162float(h3));
    uint2 hv = make_uint2(pk2(h0, h1), pk2(h2, h3));
    uint2 lv = make_uint2(pk2(l0, l1), pk2(l2, l3));
    size_t base = row * (size_t)KSPLIT + c;
    *(uint2*)(Y + base)           = hv;
    *(uint2*)(Y + base + off_lo)  = lv;
    *(uint2*)(Y + base + off_hi2) = hv;
}

// ---------------------------------------------------------------------------
// bf16 HMMA GEMM:  C[8192,1024] = A3[8192,3072] @ W3[1024,3072]^T + bias
// CTA 128x128, BK=32, 3-stage cp.async pipeline, 8 warps, warp tile 64x32.
// smem per stage: A 128x32 bf16 (8KB) + B 128x32 bf16 (8KB).
// Swizzle: 16B chunk c (0..3) within 64B row stored at c ^ ((row>>1)&3).
// ---------------------------------------------------------------------------
__global__ __launch_bounds__(256, 2)
void gemm_hmma(const __nv_bfloat16* __restrict__ A, const __nv_bfloat16* __restrict__ W,
               const float* __restrict__ bias, float* __restrict__ C)
{
    __shared__ __align__(1024) char smem_raw[3 * 16384];
    const uint32_t sbase = smem_u32(smem_raw);

    const int tid  = threadIdx.x;
    const int lane = tid & 31;
    const int wid  = tid >> 5;
    const int wm   = wid >> 2;          // 0..1 : m-offset 64
    const int wn   = wid & 3;           // 0..3 : n-offset 32
    const int m0   = blockIdx.y * 128;
    const int n0   = blockIdx.x * 128;

    const __nv_bfloat16* Ap = A + (size_t)m0 * KSPLIT;
    const __nv_bfloat16* Wp = W + (size_t)n0 * KSPLIT;

    // loader: each thread copies 2 A-chunks + 2 B-chunks (16B each) per stage
    const int lrow = tid >> 2;          // 0..63
    const int lc   = tid & 3;           // chunk in row

    // ldmatrix per-thread geometry (constant across k-iters)
    const int arow  = wm * 64 + (lane & 15);
    const int akh   = lane >> 4;                          // k-half for A
    const int aswz  = (arow >> 1) & 3;
    const int brow  = wn * 32 + (lane & 7) + ((lane & 16) ? 8 : 0);
    const int bkh   = (lane >> 3) & 1;                    // k-half for B
    const int bswz  = (brow >> 1) & 3;

    float acc[4][4][4];
    #pragma unroll
    for (int i = 0; i < 4; i++)
        #pragma unroll
        for (int j = 0; j < 4; j++)
            #pragma unroll
            for (int k = 0; k < 4; k++) acc[i][j][k] = 0.f;

    // ---- prologue: fill 3 stages ----
    #pragma unroll
    for (int s = 0; s < 3; s++) {
        uint32_t sA = sbase + s * 16384;
        uint32_t sB = sA + 8192;
        const __nv_bfloat16* ag = Ap + (size_t)s * BK + lc * 8;
        const __nv_bfloat16* wg = Wp + (size_t)s * BK + lc * 8;
        #pragma unroll
        for (int h = 0; h < 2; h++) {
            int r  = lrow + h * 64;
            int cs = lc ^ ((r >> 1) & 3);
            CP_ASYNC16(sA + r * 64 + cs * 16, ag + (size_t)r * KSPLIT);
            CP_ASYNC16(sB + r * 64 + cs * 16, wg + (size_t)r * KSPLIT);
        }
        CP_COMMIT();
    }

    int st = 0;
    for (int it = 0; it < NITER; it++) {
        CP_WAIT2();
        __syncthreads();

        const uint32_t sA = sbase + st * 16384;
        const uint32_t sB = sA + 8192;

        #pragma unroll
        for (int ks = 0; ks < 2; ks++) {
            uint32_t a[4][4];
            uint32_t b[4][2];
            const int ac = ((ks * 2 + akh) ^ aswz) * 16;
            const int bc = ((ks * 2 + bkh) ^ bswz) * 16;
            #pragma unroll
            for (int mi = 0; mi < 4; mi++)
                ldsm4(a[mi], sA + (arow + mi * 16) * 64 + ac);
            #pragma unroll
            for (int nj = 0; nj < 2; nj++) {
                uint32_t t4[4];
                ldsm4(t4, sB + (brow + nj * 16) * 64 + bc);
                b[nj * 2][0]     = t4[0]; b[nj * 2][1]     = t4[1];
                b[nj * 2 + 1][0] = t4[2]; b[nj * 2 + 1][1] = t4[3];
            }
            #pragma unroll
            for (int mi = 0; mi < 4; mi++)
                #pragma unroll
                for (int ni = 0; ni < 4; ni++)
                    mma16816(acc[mi][ni], a[mi], b[ni]);
        }
        __syncthreads();

        if (it + 3 < NITER) {
            const __nv_bfloat16* ag = Ap + (size_t)(it + 3) * BK + lc * 8;
            const __nv_bfloat16* wg = Wp + (size_t)(it + 3) * BK + lc * 8;
            #pragma unroll
            for (int h = 0; h < 2; h++) {
                int r  = lrow + h * 64;
                int cs = lc ^ ((r >> 1) & 3);
                CP_ASYNC16(sA + r * 64 + cs * 16, ag + (size_t)r * KSPLIT);
                CP_ASYNC16(sB + r * 64 + cs * 16, wg + (size_t)r * KSPLIT);
            }
        }
        CP_COMMIT();   // commit every iter (possibly empty) to keep group count fixed
        st = (st == 2) ? 0 : st + 1;
    }

    // ---- epilogue: acc + bias -> C ----
    const int trow = lane >> 2;
    const int tcol = (lane & 3) * 2;
    #pragma unroll
    for (int mi = 0; mi < 4; mi++) {
        int rbase = m0 + wm * 64 + mi * 16 + trow;
        #pragma unroll
        for (int ni = 0; ni < 4; ni++) {
            int col = n0 + wn * 32 + ni * 8 + tcol;
            float b0 = __ldg(bias + col), b1 = __ldg(bias + col + 1);
            float2 v0 = make_float2(acc[mi][ni][0] + b0, acc[mi][ni][1] + b1);
            float2 v1 = make_float2(acc[mi][ni][2] + b0, acc[mi][ni][3] + b1);
            *(float2*)(C + (size_t)rbase * EMB + col)       = v0;
            *(float2*)(C + (size_t)(rbase + 8) * EMB + col) = v1;
        }
    }
}

// ---------------------------------------------------------------------------
// Flash attention (causal), fp32 — unchanged from R1.
// ---------------------------------------------------------------------------
#define NEG_BIG (-1e30f)

__global__ __launch_bounds__(256)
void attn_kernel(const float* __restrict__ Q, const float* __restrict__ K,
                 const float* __restrict__ V, float* __restrict__ O)
{
    extern __shared__ float smf[];
    float* Qs = smf;
    float* Ks = Qs + 64 * 65;
    float* Vs = Ks + 64 * 65;
    float* Ps = Vs + 64 * 65;
    float* Ms = Ps + 64 * 65;
    float* Ls = Ms + 64;

    const int tid = threadIdx.x;
    const int tx  = tid & 15;
    const int ty  = tid >> 4;
    const int qb  = blockIdx.x * 64;
    const int h   = blockIdx.y;
    const int b   = blockIdx.z;
    const size_t base = ((size_t)b * SEQ) * EMB + (size_t)h * HD;

    #pragma unroll
    for (int t = 0; t < 4; t++) {
        int idx = tid + t * 256;
        int r   = idx >> 4;
        int c   = (idx & 15) << 2;
        float4 v = *(const float4*)(Q + base + (size_t)(qb + r) * EMB + c);
        Qs[r * 65 + c + 0] = v.x * 0.125f;
        Qs[r * 65 + c + 1] = v.y * 0.125f;
        Qs[r * 65 + c + 2] = v.z * 0.125f;
        Qs[r * 65 + c + 3] = v.w * 0.125f;
    }
    if (tid < 64) { Ms[tid] = NEG_BIG; Ls[tid] = 0.f; }

    float acc[4][4];
    #pragma unroll
    for (int i = 0; i < 4; i++)
        #pragma unroll
        for (int j = 0; j < 4; j++) acc[i][j] = 0.f;

    const int nk = blockIdx.x + 1;
    for (int kb = 0; kb < nk; kb++) {
        const int kbase = kb * 64;
        __syncthreads();
        #pragma unroll
        for (int t = 0; t < 4; t++) {
            int idx = tid + t * 256;
            int r   = idx >> 4;
            int c   = (idx & 15) << 2;
            float4 vk = *(const float4*)(K + base + (size_t)(kbase + r) * EMB + c);
            Ks[r * 65 + c + 0] = vk.x; Ks[r * 65 + c + 1] = vk.y;
            Ks[r * 65 + c + 2] = vk.z; Ks[r * 65 + c + 3] = vk.w;
            float4 vv = *(const float4*)(V + base + (size_t)(kbase + r) * EMB + c);
            Vs[r * 65 + c + 0] = vv.x; Vs[r * 65 + c + 1] = vv.y;
            Vs[r * 65 + c + 2] = vv.z; Vs[r * 65 + c + 3] = vv.w;
        }
        __syncthreads();

        float s[4][4];
        #pragma unroll
        for (int i = 0; i < 4; i++)
            #pragma unroll
            for (int j = 0; j < 4; j++) s[i][j] = 0.f;

        #pragma unroll 16
        for (int d = 0; d < 64; d++) {
            float a0 = Qs[(ty * 4 + 0) * 65 + d];
            float a1 = Qs[(ty * 4 + 1) * 65 + d];
            float a2 = Qs[(ty * 4 + 2) * 65 + d];
            float a3 = Qs[(ty * 4 + 3) * 65 + d];
            float b0 = Ks[(tx * 4 + 0) * 65 + d];
            float b1 = Ks[(tx * 4 + 1) * 65 + d];
            float b2 = Ks[(tx * 4 + 2) * 65 + d];
            float b3 = Ks[(tx * 4 + 3) * 65 + d];
            s[0][0] += a0 * b0; s[0][1] += a0 * b1; s[0][2] += a0 * b2; s[0][3] += a0 * b3;
            s[1][0] += a1 * b0; s[1][1] += a1 * b1; s[1][2] += a1 * b2; s[1][3] += a1 * b3;
            s[2][0] += a2 * b0; s[2][1] += a2 * b1; s[2][2] += a2 * b2; s[2][3] += a2 * b3;
            s[3][0] += a3 * b0; s[3][1] += a3 * b1; s[3][2] += a3 * b2; s[3][3] += a3 * b3;
        }

        if (kb == nk - 1) {
            #pragma unroll
            for (int i = 0; i < 4; i++) {
                int qrow = qb + ty * 4 + i;
                #pragma unroll
                for (int j = 0; j < 4; j++) {
                    int kcol = kbase + tx * 4 + j;
                    if (kcol > qrow) s[i][j] = NEG_BIG;
                }
            }
        }

        #pragma unroll
        for (int i = 0; i < 4; i++) {
            const int row = ty * 4 + i;
            float mloc = fmaxf(fmaxf(s[i][0], s[i][1]), fmaxf(s[i][2], s[i][3]));
            #pragma unroll
            for (int off = 8; off; off >>= 1)
                mloc = fmaxf(mloc, __shfl_xor_sync(0xffffffffu, mloc, off));
            float mold = Ms[row];
            float mnew = fmaxf(mold, mloc);
            float corr = __expf(mold - mnew);
            float psum = 0.f;
            #pragma unroll
            for (int j = 0; j < 4; j++) {
                float p = __expf(s[i][j] - mnew);
                Ps[(tx * 4 + j) * 65 + row] = p;
                psum += p;
                acc[i][j] *= corr;
            }
            #pragma unroll
            for (int off = 8; off; off >>= 1)
                psum += __shfl_xor_sync(0xffffffffu, psum, off);
            __syncwarp();
            if (tx == 0) { Ms[row] = mnew; Ls[row] = Ls[row] * corr + psum; }
        }
        __syncthreads();

        #pragma unroll 16
        for (int c = 0; c < 64; c++) {
            float p0 = Ps[c * 65 + ty * 4 + 0];
            float p1 = Ps[c * 65 + ty * 4 + 1];
            float p2 = Ps[c * 65 + ty * 4 + 2];
            float p3 = Ps[c * 65 + ty * 4 + 3];
            float v0 = Vs[c * 65 + tx * 4 + 0];
            float v1 = Vs[c * 65 + tx * 4 + 1];
            float v2 = Vs[c * 65 + tx * 4 + 2];
            float v3 = Vs[c * 65 + tx * 4 + 3];
            acc[0][0] += p0 * v0; acc[0][1] += p0 * v1; acc[0][2] += p0 * v2; acc[0][3] += p0 * v3;
            acc[1][0] += p1 * v0; acc[1][1] += p1 * v1; acc[1][2] += p1 * v2; acc[1][3] += p1 * v3;
            acc[2][0] += p2 * v0; acc[2][1] += p2 * v1; acc[2][2] += p2 * v2; acc[2][3] += p2 * v3;
            acc[3][0] += p3 * v0; acc[3][1] += p3 * v1; acc[3][2] += p3 * v2; acc[3][3] += p3 * v3;
        }
    }
    __syncthreads();

    #pragma unroll
    for (int i = 0; i < 4; i++) {
        int row = ty * 4 + i;
        float inv = 1.f / Ls[row];
        float4 o;
        o.x = acc[i][0] * inv; o.y = acc[i][1] * inv;
        o.z = acc[i][2] * inv; o.w = acc[i][3] * inv;
        *(float4*)(O + base + (size_t)(qb + row) * EMB + tx * 4) = o;
    }
}

// ---------------------------------------------------------------------------
extern "C" void kernel_launch(void* const* d_in, const int* in_sizes, int n_in,
                              void* d_out, int out_size)
{
    const float* query = (const float*)d_in[0];
    const float* key   = (const float*)d_in[1];
    const float* value = (const float*)d_in[2];
    const float* Wq = (const float*)d_in[4];  const float* bq = (const float*)d_in[5];
    const float* Wk = (const float*)d_in[6];  const float* bk = (const float*)d_in[7];
    const float* Wv = (const float*)d_in[8];  const float* bv = (const float*)d_in[9];
    const float* Wo = (const float*)d_in[10]; const float* bo = (const float*)d_in[11];
    float* out = (float*)d_out;

    float *qp, *kp, *vp, *ap;
    __nv_bfloat16 *a3p, *w3p;
    cudaGetSymbolAddress((void**)&qp, g_q);
    cudaGetSymbolAddress((void**)&kp, g_k);
    cudaGetSymbolAddress((void**)&vp, g_v);
    cudaGetSymbolAddress((void**)&ap, g_a);
    cudaGetSymbolAddress((void**)&a3p, g_a3);
    cudaGetSymbolAddress((void**)&w3p, g_w3);

    __nv_bfloat16* w3[4] = { w3p,
                             w3p + (size_t)EMB * KSPLIT,
                             w3p + 2 * (size_t)EMB * KSPLIT,
                             w3p + 3 * (size_t)EMB * KSPLIT };

    dim3 ggrid(EMB / 128, MTOT / 128);          // (8, 64)

    // weights -> [hi | hi | lo]
    split3<<<EMB, 256>>>(Wq, w3[0], 2048, 1024);
    split3<<<EMB, 256>>>(Wk, w3[1], 2048, 1024);
    split3<<<EMB, 256>>>(Wv, w3[2], 2048, 1024);
    split3<<<EMB, 256>>>(Wo, w3[3], 2048, 1024);

    // activations -> [hi | lo | hi], then GEMM
    split3<<<MTOT, 256>>>(query, a3p, 1024, 2048);
    gemm_hmma<<<ggrid, 256>>>(a3p, w3[0], bq, qp);
    split3<<<MTOT, 256>>>(key, a3p, 1024, 2048);
    gemm_hmma<<<ggrid, 256>>>(a3p, w3[1], bk, kp);
    split3<<<MTOT, 256>>>(value, a3p, 1024, 2048);
    gemm_hmma<<<ggrid, 256>>>(a3p, w3[2], bv, vp);

    int asm_b = (4 * 64 * 65 + 128) * (int)sizeof(float);
    cudaFuncSetAttribute(attn_kernel, cudaFuncAttributeMaxDynamicSharedMemorySize, asm_b);
    attn_kernel<<<dim3(SEQ / 64, NH, BATCH), 256, asm_b>>>(qp, kp, vp, ap);

    split3<<<MTOT, 256>>>(ap, a3p, 1024, 2048);
    gemm_hmma<<<ggrid, 256>>>(a3p, w3[3], bo, out);
}

// round 5
// speedup vs baseline: 2.9881x; 1.8129x over previous
#include <cuda_runtime.h>
#include <cuda_bf16.h>
#include <cstdint>
#include <cstddef>

#define BATCH 4
#define SEQ   2048
#define EMB   1024
#define NH    16
#define HD    64
#define MTOT  (BATCH * SEQ)        /* 8192 */
#define KSPLIT (3 * EMB)           /* 3072 */
#define BK    32
#define NITER (KSPLIT / BK)        /* 96 */
#define LOG2E 1.44269504f
#define NEG_BIG (-1e30f)
#define BHS   ((size_t)BATCH * NH * SEQ)   /* 131072 rows of per-head layout */

// ---------------- scratch (__device__ globals; no allocs) -------------------
__device__ __align__(1024) float g_q[(size_t)MTOT * EMB];
__device__ __align__(1024) float g_k[(size_t)MTOT * EMB];
__device__ __align__(1024) float g_v[(size_t)MTOT * EMB];
__device__ __align__(1024) __nv_bfloat16 g_a3[(size_t)MTOT * KSPLIT];   // 48MB
__device__ __align__(1024) __nv_bfloat16 g_w3[4][(size_t)EMB * KSPLIT]; // 4x6MB
__device__ __align__(1024) __nv_bfloat16 g_q3[BHS * 192];   // [b,h,s,192] 48MB
__device__ __align__(1024) __nv_bfloat16 g_k3[BHS * 192];   // 48MB
__device__ __align__(1024) __nv_bfloat16 g_vh[BHS * HD];    // [b,h,s,64] 16MB
__device__ __align__(1024) __nv_bfloat16 g_vl[BHS * HD];    // 16MB

// ---------------- PTX helpers (baseline ISA: sm_80-era ops) -----------------
__device__ __forceinline__ uint32_t smem_u32(const void* p) {
    uint32_t a;
    asm("{ .reg .u64 t; cvta.to.shared.u64 t, %1; cvt.u32.u64 %0, t; }" : "=r"(a) : "l"(p));
    return a;
}
#define CP_ASYNC16(dst, src) \
    asm volatile("cp.async.cg.shared.global [%0], [%1], 16;" :: "r"(dst), "l"(src) : "memory")
#define CP_COMMIT() asm volatile("cp.async.commit_group;" ::: "memory")
#define CP_WAIT1()  asm volatile("cp.async.wait_group 1;" ::: "memory")
#define CP_WAIT2()  asm volatile("cp.async.wait_group 2;" ::: "memory")

__device__ __forceinline__ void ldsm4(uint32_t (&r)[4], uint32_t addr) {
    asm volatile("ldmatrix.sync.aligned.m8n8.x4.shared.b16 {%0,%1,%2,%3}, [%4];"
                 : "=r"(r[0]), "=r"(r[1]), "=r"(r[2]), "=r"(r[3]) : "r"(addr));
}
__device__ __forceinline__ void ldsm4t(uint32_t (&r)[4], uint32_t addr) {
    asm volatile("ldmatrix.sync.aligned.m8n8.x4.trans.shared.b16 {%0,%1,%2,%3}, [%4];"
                 : "=r"(r[0]), "=r"(r[1]), "=r"(r[2]), "=r"(r[3]) : "r"(addr));
}
__device__ __forceinline__ void mma16816(float (&d)[4], const uint32_t (&a)[4],
                                         uint32_t b0, uint32_t b1) {
    asm volatile(
        "mma.sync.aligned.m16n8k16.row.col.f32.bf16.bf16.f32 "
        "{%0,%1,%2,%3}, {%4,%5,%6,%7}, {%8,%9}, {%0,%1,%2,%3};"
        : "+f"(d[0]), "+f"(d[1]), "+f"(d[2]), "+f"(d[3])
        : "r"(a[0]), "r"(a[1]), "r"(a[2]), "r"(a[3]), "r"(b0), "r"(b1));
}
__device__ __forceinline__ uint32_t pk2(__nv_bfloat16 a, __nv_bfloat16 b) {
    __nv_bfloat162 t = __halves2bfloat162(a, b);
    return *reinterpret_cast<uint32_t*>(&t);
}

// ---------------------------------------------------------------------------
// split3: fp32 -> bf16 hi/lo, 3 K-blocks of a 3072-wide row.
// ---------------------------------------------------------------------------
__global__ __launch_bounds__(256)
void split3(const float* __restrict__ X, __nv_bfloat16* __restrict__ Y,
            int off_lo, int off_hi2)
{
    size_t idx = (size_t)blockIdx.x * 256 + threadIdx.x;
    size_t row = idx >> 8;
    int    c   = (int)(idx & 255) << 2;
    float4 x = ((const float4*)X)[idx];
    __nv_bfloat16 h0 = __float2bfloat16(x.x), h1 = __float2bfloat16(x.y);
    __nv_bfloat16 h2 = __float2bfloat16(x.z), h3 = __float2bfloat16(x.w);
    __nv_bfloat16 l0 = __float2bfloat16(x.x - __bfloat162float(h0));
    __nv_bfloat16 l1 = __float2bfloat16(x.y - __bfloat162float(h1));
    __nv_bfloat16 l2 = __float2bfloat16(x.z - __bfloat162float(h2));
    __nv_bfloat16 l3 = __float2bfloat16(x.w - __bfloat162float(h3));
    uint2 hv = make_uint2(pk2(h0, h1), pk2(h2, h3));
    uint2 lv = make_uint2(pk2(l0, l1), pk2(l2, l3));
    size_t base = row * (size_t)KSPLIT + c;
    *(uint2*)(Y + base)           = hv;
    *(uint2*)(Y + base + off_lo)  = lv;
    *(uint2*)(Y + base + off_hi2) = hv;
}

// ---------------------------------------------------------------------------
// t_qk: fp32 [b*2048+s][1024] -> bf16 [(b*16+h)*2048+s][192] split layout.
// ---------------------------------------------------------------------------
__global__ __launch_bounds__(256)
void t_qk(const float* __restrict__ X, __nv_bfloat16* __restrict__ Y,
          float scale, int off_lo, int off_hi2)
{
    int row = blockIdx.x;
    int tid = threadIdx.x;
    int hh = tid >> 4, d0 = (tid & 15) << 2;
    float4 x = *(const float4*)(X + (size_t)row * EMB + hh * 64 + d0);
    x.x *= scale; x.y *= scale; x.z *= scale; x.w *= scale;
    __nv_bfloat16 h0 = __float2bfloat16(x.x), h1 = __float2bfloat16(x.y);
    __nv_bfloat16 h2 = __float2bfloat16(x.z), h3 = __float2bfloat16(x.w);
    __nv_bfloat16 l0 = __float2bfloat16(x.x - __bfloat162float(h0));
    __nv_bfloat16 l1 = __float2bfloat16(x.y - __bfloat162float(h1));
    __nv_bfloat16 l2 = __float2bfloat16(x.z - __bfloat162float(h2));
    __nv_bfloat16 l3 = __float2bfloat16(x.w - __bfloat162float(h3));
    uint2 hv = make_uint2(pk2(h0, h1), pk2(h2, h3));
    uint2 lv = make_uint2(pk2(l0, l1), pk2(l2, l3));
    size_t drow = ((size_t)((row >> 11) * NH + hh)) * SEQ + (row & 2047);
    size_t base = drow * 192 + d0;
    *(uint2*)(Y + base)           = hv;
    *(uint2*)(Y + base + off_lo)  = lv;
    *(uint2*)(Y + base + off_hi2) = hv;
}

// t_v: fp32 -> vh/vl [b,h,s,64]
__global__ __launch_bounds__(256)
void t_v(const float* __restrict__ X, __nv_bfloat16* __restrict__ VHo,
         __nv_bfloat16* __restrict__ VLo)
{
    int row = blockIdx.x;
    int tid = threadIdx.x;
    int hh = tid >> 4, d0 = (tid & 15) << 2;
    float4 x = *(const float4*)(X + (size_t)row * EMB + hh * 64 + d0);
    __nv_bfloat16 h0 = __float2bfloat16(x.x), h1 = __float2bfloat16(x.y);
    __nv_bfloat16 h2 = __float2bfloat16(x.z), h3 = __float2bfloat16(x.w);
    __nv_bfloat16 l0 = __float2bfloat16(x.x - __bfloat162float(h0));
    __nv_bfloat16 l1 = __float2bfloat16(x.y - __bfloat162float(h1));
    __nv_bfloat16 l2 = __float2bfloat16(x.z - __bfloat162float(h2));
    __nv_bfloat16 l3 = __float2bfloat16(x.w - __bfloat162float(h3));
    size_t drow = ((size_t)((row >> 11) * NH + hh)) * SEQ + (row & 2047);
    *(uint2*)(VHo + drow * HD + d0) = make_uint2(pk2(h0, h1), pk2(h2, h3));
    *(uint2*)(VLo + drow * HD + d0) = make_uint2(pk2(l0, l1), pk2(l2, l3));
}

// ---------------------------------------------------------------------------
// bf16 HMMA GEMM: C[8192,1024] = A3[8192,3072] @ W3[1024,3072]^T + bias
// ---------------------------------------------------------------------------
__global__ __launch_bounds__(256, 2)
void gemm_hmma(const __nv_bfloat16* __restrict__ A, const __nv_bfloat16* __restrict__ W,
               const float* __restrict__ bias, float* __restrict__ C)
{
    __shared__ __align__(1024) char smem_raw[3 * 16384];
    const uint32_t sbase = smem_u32(smem_raw);

    const int tid  = threadIdx.x;
    const int lane = tid & 31;
    const int wid  = tid >> 5;
    const int wm   = wid >> 2;
    const int wn   = wid & 3;
    const int m0   = blockIdx.y * 128;
    const int n0   = blockIdx.x * 128;

    const __nv_bfloat16* Ap = A + (size_t)m0 * KSPLIT;
    const __nv_bfloat16* Wp = W + (size_t)n0 * KSPLIT;

    const int lrow = tid >> 2;
    const int lc   = tid & 3;

    const int arow  = wm * 64 + (lane & 15);
    const int akh   = lane >> 4;
    const int aswz  = (arow >> 1) & 3;
    const int brow  = wn * 32 + (lane & 7) + ((lane & 16) ? 8 : 0);
    const int bkh   = (lane >> 3) & 1;
    const int bswz  = (brow >> 1) & 3;

    float acc[4][4][4];
    #pragma unroll
    for (int i = 0; i < 4; i++)
        #pragma unroll
        for (int j = 0; j < 4; j++)
            #pragma unroll
            for (int k = 0; k < 4; k++) acc[i][j][k] = 0.f;

    #pragma unroll
    for (int s = 0; s < 3; s++) {
        uint32_t sA = sbase + s * 16384;
        uint32_t sB = sA + 8192;
        const __nv_bfloat16* ag = Ap + (size_t)s * BK + lc * 8;
        const __nv_bfloat16* wg = Wp + (size_t)s * BK + lc * 8;
        #pragma unroll
        for (int h = 0; h < 2; h++) {
            int r  = lrow + h * 64;
            int cs = lc ^ ((r >> 1) & 3);
            CP_ASYNC16(sA + r * 64 + cs * 16, ag + (size_t)r * KSPLIT);
            CP_ASYNC16(sB + r * 64 + cs * 16, wg + (size_t)r * KSPLIT);
        }
        CP_COMMIT();
    }

    int st = 0;
    for (int it = 0; it < NITER; it++) {
        CP_WAIT2();
        __syncthreads();

        const uint32_t sA = sbase + st * 16384;
        const uint32_t sB = sA + 8192;

        #pragma unroll
        for (int ks = 0; ks < 2; ks++) {
            uint32_t a[4][4];
            uint32_t b[4][2];
            const int ac = ((ks * 2 + akh) ^ aswz) * 16;
            const int bc = ((ks * 2 + bkh) ^ bswz) * 16;
            #pragma unroll
            for (int mi = 0; mi < 4; mi++)
                ldsm4(a[mi], sA + (arow + mi * 16) * 64 + ac);
            #pragma unroll
            for (int nj = 0; nj < 2; nj++) {
                uint32_t t4[4];
                ldsm4(t4, sB + (brow + nj * 16) * 64 + bc);
                b[nj * 2][0]     = t4[0]; b[nj * 2][1]     = t4[1];
                b[nj * 2 + 1][0] = t4[2]; b[nj * 2 + 1][1] = t4[3];
            }
            #pragma unroll
            for (int mi = 0; mi < 4; mi++)
                #pragma unroll
                for (int ni = 0; ni < 4; ni++)
                    mma16816(acc[mi][ni], a[mi], b[ni][0], b[ni][1]);
        }
        __syncthreads();

        if (it + 3 < NITER) {
            const __nv_bfloat16* ag = Ap + (size_t)(it + 3) * BK + lc * 8;
            const __nv_bfloat16* wg = Wp + (size_t)(it + 3) * BK + lc * 8;
            #pragma unroll
            for (int h = 0; h < 2; h++) {
                int r  = lrow + h * 64;
                int cs = lc ^ ((r >> 1) & 3);
                CP_ASYNC16(sA + r * 64 + cs * 16, ag + (size_t)r * KSPLIT);
                CP_ASYNC16(sB + r * 64 + cs * 16, wg + (size_t)r * KSPLIT);
            }
        }
        CP_COMMIT();
        st = (st == 2) ? 0 : st + 1;
    }

    const int trow = lane >> 2;
    const int tcol = (lane & 3) * 2;
    #pragma unroll
    for (int mi = 0; mi < 4; mi++) {
        int rbase = m0 + wm * 64 + mi * 16 + trow;
        #pragma unroll
        for (int ni = 0; ni < 4; ni++) {
            int col = n0 + wn * 32 + ni * 8 + tcol;
            float b0 = __ldg(bias + col), b1 = __ldg(bias + col + 1);
            float2 v0 = make_float2(acc[mi][ni][0] + b0, acc[mi][ni][1] + b1);
            float2 v1 = make_float2(acc[mi][ni][2] + b0, acc[mi][ni][3] + b1);
            *(float2*)(C + (size_t)rbase * EMB + col)       = v0;
            *(float2*)(C + (size_t)(rbase + 8) * EMB + col) = v1;
        }
    }
}

// ---------------------------------------------------------------------------
// HMMA flash attention (causal), bf16 3-term split, fp32 accum.
// Block: 128 queries x 1 head. 8 warps x 16 rows. Key tiles of 64.
// smem: Q 48KB | K3 2x24KB | V(h+l) 2x16KB = 128KB.
// Epilogue writes a3 [hi|lo|hi] rows directly.
// ---------------------------------------------------------------------------
__global__ __launch_bounds__(256, 1)
void attn_hmma(const __nv_bfloat16* __restrict__ Q3, const __nv_bfloat16* __restrict__ K3,
               const __nv_bfloat16* __restrict__ VH, const __nv_bfloat16* __restrict__ VL,
               __nv_bfloat16* __restrict__ A3)
{
    extern __shared__ __align__(1024) char smr[];
    const uint32_t sb = smem_u32(smr);
    const uint32_t QS = sb;                 // 6 slabs * 8192B
    const uint32_t KS = sb + 49152;         // 2 stages * 24576
    const uint32_t VS = sb + 98304;         // 2 stages * 16384 (vh 8KB + vl 8KB)

    const int tid  = threadIdx.x;
    const int lane = tid & 31;
    const int wid  = tid >> 5;
    const int bx   = blockIdx.x;
    const int head = blockIdx.y;
    const int bz   = blockIdx.z;
    const int qb0  = bx * 128;
    const size_t bh = (size_t)(bz * NH + head);
    const int nkb  = 2 * bx + 2;

    const __nv_bfloat16* Qp = Q3 + (bh * SEQ + qb0) * 192;
    const __nv_bfloat16* Kp = K3 + bh * SEQ * 192;
    const __nv_bfloat16* VHp = VH + bh * SEQ * HD;
    const __nv_bfloat16* VLp = VL + bh * SEQ * HD;

    // ---- load Q (all 6 slabs) + stage 0 K/V, one commit group ----
    {
        const int r1 = tid >> 2, lc = tid & 3;
        #pragma unroll
        for (int kc = 0; kc < 6; kc++)
            #pragma unroll
            for (int h = 0; h < 2; h++) {
                int r = r1 + h * 64;
                int cs = lc ^ ((r >> 1) & 3);
                CP_ASYNC16(QS + kc * 8192 + r * 64 + cs * 16,
                           Qp + (size_t)r * 192 + kc * 32 + lc * 8);
            }
        int cs = lc ^ ((r1 >> 1) & 3);
        #pragma unroll
        for (int kc = 0; kc < 6; kc++)
            CP_ASYNC16(KS + kc * 4096 + r1 * 64 + cs * 16,
                       Kp + (size_t)r1 * 192 + kc * 32 + lc * 8);
        const int vr = tid >> 3, vc = tid & 7;
        #pragma unroll
        for (int h = 0; h < 2; h++) {
            int r = vr + h * 32;
            int pc = vc ^ (r & 7);
            CP_ASYNC16(VS + r * 128 + pc * 16, VHp + (size_t)r * HD + vc * 8);
            CP_ASYNC16(VS + 8192 + r * 128 + pc * 16, VLp + (size_t)r * HD + vc * 8);
        }
        CP_COMMIT();
    }

    const int arow = wid * 16 + (lane & 15);
    const int akh  = lane >> 4;
    const int aswz = (arow >> 1) & 3;
    const int brow = (lane & 7) + ((lane & 16) ? 8 : 0);
    const int bkh  = (lane >> 3) & 1;
    const int bswz = (brow >> 1) & 3;
    const int vrow = (lane & 7) + 8 * ((lane >> 3) & 1);
    const int vchb = lane >> 4;
    const int vswz = lane & 7;

    float of[8][4];
    #pragma unroll
    for (int i = 0; i < 8; i++)
        #pragma unroll
        for (int j = 0; j < 4; j++) of[i][j] = 0.f;
    float mq[2] = { NEG_BIG, NEG_BIG };
    float lq[2] = { 0.f, 0.f };

    const int qrow0 = qb0 + wid * 16 + (lane >> 2);

    for (int kb = 0; kb < nkb; kb++) {
        const int st = kb & 1;
        const int kbase = kb * 64;

        if (kb + 1 < nkb) {
            const int nb = (kb + 1) * 64;
            const int s2 = st ^ 1;
            const int r1 = tid >> 2, lc = tid & 3;
            int cs = lc ^ ((r1 >> 1) & 3);
            #pragma unroll
            for (int kc = 0; kc < 6; kc++)
                CP_ASYNC16(KS + s2 * 24576 + kc * 4096 + r1 * 64 + cs * 16,
                           Kp + (size_t)(nb + r1) * 192 + kc * 32 + lc * 8);
            const int vr = tid >> 3, vc = tid & 7;
            #pragma unroll
            for (int h = 0; h < 2; h++) {
                int r = vr + h * 32;
                int pc = vc ^ (r & 7);
                CP_ASYNC16(VS + s2 * 16384 + r * 128 + pc * 16,
                           VHp + (size_t)(nb + r) * HD + vc * 8);
                CP_ASYNC16(VS + s2 * 16384 + 8192 + r * 128 + pc * 16,
                           VLp + (size_t)(nb + r) * HD + vc * 8);
            }
        }
        CP_COMMIT();
        CP_WAIT1();
        __syncthreads();

        // ---- S = Q3 . K3^T  (K=192) ----
        float sf[8][4];
        #pragma unroll
        for (int i = 0; i < 8; i++)
            #pragma unroll
            for (int j = 0; j < 4; j++) sf[i][j] = 0.f;

        const uint32_t Kst = KS + st * 24576;
        #pragma unroll
        for (int kc = 0; kc < 6; kc++) {
            #pragma unroll
            for (int ks = 0; ks < 2; ks++) {
                uint32_t a[4];
                ldsm4(a, QS + kc * 8192 + arow * 64 + (((ks * 2 + akh) ^ aswz) * 16));
                const int bc = ((ks * 2 + bkh) ^ bswz) * 16;
                #pragma unroll
                for (int np = 0; np < 4; np++) {
                    uint32_t t4[4];
                    ldsm4(t4, Kst + kc * 4096 + (np * 16 + brow) * 64 + bc);
                    mma16816(sf[2 * np],     a, t4[0], t4[1]);
                    mma16816(sf[2 * np + 1], a, t4[2], t4[3]);
                }
            }
        }

        if (kb >= nkb - 2) {
            #pragma unroll
            for (int nt = 0; nt < 8; nt++) {
                int col = kbase + nt * 8 + 2 * (lane & 3);
                if (col     > qrow0)     sf[nt][0] = NEG_BIG;
                if (col + 1 > qrow0)     sf[nt][1] = NEG_BIG;
                if (col     > qrow0 + 8) sf[nt][2] = NEG_BIG;
                if (col + 1 > qrow0 + 8) sf[nt][3] = NEG_BIG;
            }
        }

        #pragma unroll
        for (int h = 0; h < 2; h++) {
            float mloc = NEG_BIG;
            #pragma unroll
            for (int nt = 0; nt < 8; nt++)
                mloc = fmaxf(mloc, fmaxf(sf[nt][2 * h], sf[nt][2 * h + 1]));
            mloc = fmaxf(mloc, __shfl_xor_sync(0xffffffffu, mloc, 1));
            mloc = fmaxf(mloc, __shfl_xor_sync(0xffffffffu, mloc, 2));
            float mnew = fmaxf(mq[h], mloc);
            float corr = exp2f((mq[h] - mnew) * LOG2E);
            mq[h] = mnew;
            lq[h] *= corr;
            float ps = 0.f;
            #pragma unroll
            for (int nt = 0; nt < 8; nt++) {
                float p0 = exp2f((sf[nt][2 * h] - mnew) * LOG2E);
                float p1 = exp2f((sf[nt][2 * h + 1] - mnew) * LOG2E);
                sf[nt][2 * h] = p0; sf[nt][2 * h + 1] = p1;
                ps += p0 + p1;
                of[nt][2 * h] *= corr; of[nt][2 * h + 1] *= corr;
            }
            ps += __shfl_xor_sync(0xffffffffu, ps, 1);
            ps += __shfl_xor_sync(0xffffffffu, ps, 2);
            lq[h] += ps;
        }

        // ---- O += P.V  (ph*vh + pl*vh + ph*vl) ----
        const uint32_t Vst = VS + st * 16384;
        #pragma unroll
        for (int kc2 = 0; kc2 < 4; kc2++) {
            const int j0 = 2 * kc2, j1 = j0 + 1;
            uint32_t ph[4], pl[4];
            #pragma unroll
            for (int q = 0; q < 4; q++) {
                const float p0 = (q & 2) ? sf[j1][(q & 1) * 2]     : sf[j0][(q & 1) * 2];
                const float p1 = (q & 2) ? sf[j1][(q & 1) * 2 + 1] : sf[j0][(q & 1) * 2 + 1];
                __nv_bfloat16 h0 = __float2bfloat16(p0), h1 = __float2bfloat16(p1);
                ph[q] = pk2(h0, h1);
                pl[q] = pk2(__float2bfloat16(p0 - __bfloat162float(h0)),
                            __float2bfloat16(p1 - __bfloat162float(h1)));
            }
            const uint32_t rowoff = (kc2 * 16 + vrow) * 128;
            #pragma unroll
            for (int np = 0; np < 4; np++) {
                const int pc = (2 * np + vchb) ^ vswz;
                uint32_t bh4[4], bl4[4];
                ldsm4t(bh4, Vst + rowoff + pc * 16);
                ldsm4t(bl4, Vst + 8192 + rowoff + pc * 16);
                mma16816(of[2 * np],     ph, bh4[0], bh4[1]);
                mma16816(of[2 * np + 1], ph, bh4[2], bh4[3]);
                mma16816(of[2 * np],     pl, bh4[0], bh4[1]);
                mma16816(of[2 * np + 1], pl, bh4[2], bh4[3]);
                mma16816(of[2 * np],     ph, bl4[0], bl4[1]);
                mma16816(of[2 * np + 1], ph, bl4[2], bl4[3]);
            }
        }
        __syncthreads();
    }

    // ---- epilogue: normalize, split, write a3 [hi|lo|hi] ----
    const float inv0 = 1.f / lq[0];
    const float inv1 = 1.f / lq[1];
    const size_t ar0 = (size_t)bz * SEQ + qb0 + wid * 16 + (lane >> 2);
    const size_t ar1 = ar0 + 8;
    const int colb = head * 64 + 2 * (lane & 3);
    #pragma unroll
    for (int nt = 0; nt < 8; nt++) {
        int col = colb + nt * 8;
        float v0 = of[nt][0] * inv0, v1 = of[nt][1] * inv0;
        float v2 = of[nt][2] * inv1, v3 = of[nt][3] * inv1;
        __nv_bfloat16 h0 = __float2bfloat16(v0), h1 = __float2bfloat16(v1);
        __nv_bfloat16 h2 = __float2bfloat16(v2), h3 = __float2bfloat16(v3);
        uint32_t hp0 = pk2(h0, h1), hp1 = pk2(h2, h3);
        uint32_t lp0 = pk2(__float2bfloat16(v0 - __bfloat162float(h0)),
                           __float2bfloat16(v1 - __bfloat162float(h1)));
        uint32_t lp1 = pk2(__float2bfloat16(v2 - __bfloat162float(h2)),
                           __float2bfloat16(v3 - __bfloat162float(h3)));
        __nv_bfloat16* d0 = A3 + ar0 * KSPLIT + col;
        __nv_bfloat16* d1 = A3 + ar1 * KSPLIT + col;
        *(uint32_t*)(d0)        = hp0; *(uint32_t*)(d1)        = hp1;
        *(uint32_t*)(d0 + 1024) = lp0; *(uint32_t*)(d1 + 1024) = lp1;
        *(uint32_t*)(d0 + 2048) = hp0; *(uint32_t*)(d1 + 2048) = hp1;
    }
}

// ---------------------------------------------------------------------------
extern "C" void kernel_launch(void* const* d_in, const int* in_sizes, int n_in,
                              void* d_out, int out_size)
{
    const float* query = (const float*)d_in[0];
    const float* key   = (const float*)d_in[1];
    const float* value = (const float*)d_in[2];
    const float* Wq = (const float*)d_in[4];  const float* bq = (const float*)d_in[5];
    const float* Wk = (const float*)d_in[6];  const float* bk = (const float*)d_in[7];
    const float* Wv = (const float*)d_in[8];  const float* bv = (const float*)d_in[9];
    const float* Wo = (const float*)d_in[10]; const float* bo = (const float*)d_in[11];
    float* out = (float*)d_out;

    float *qp, *kp, *vp;
    __nv_bfloat16 *a3p, *w3p, *q3p, *k3p, *vhp, *vlp;
    cudaGetSymbolAddress((void**)&qp, g_q);
    cudaGetSymbolAddress((void**)&kp, g_k);
    cudaGetSymbolAddress((void**)&vp, g_v);
    cudaGetSymbolAddress((void**)&a3p, g_a3);
    cudaGetSymbolAddress((void**)&w3p, g_w3);
    cudaGetSymbolAddress((void**)&q3p, g_q3);
    cudaGetSymbolAddress((void**)&k3p, g_k3);
    cudaGetSymbolAddress((void**)&vhp, g_vh);
    cudaGetSymbolAddress((void**)&vlp, g_vl);

    __nv_bfloat16* w3[4] = { w3p,
                             w3p + (size_t)EMB * KSPLIT,
                             w3p + 2 * (size_t)EMB * KSPLIT,
                             w3p + 3 * (size_t)EMB * KSPLIT };

    dim3 ggrid(EMB / 128, MTOT / 128);

    // weights -> [hi | hi | lo]
    split3<<<EMB, 256>>>(Wq, w3[0], 2048, 1024);
    split3<<<EMB, 256>>>(Wk, w3[1], 2048, 1024);
    split3<<<EMB, 256>>>(Wv, w3[2], 2048, 1024);
    split3<<<EMB, 256>>>(Wo, w3[3], 2048, 1024);

    // projections
    split3<<<MTOT, 256>>>(query, a3p, 1024, 2048);
    gemm_hmma<<<ggrid, 256>>>(a3p, w3[0], bq, qp);
    split3<<<MTOT, 256>>>(key, a3p, 1024, 2048);
    gemm_hmma<<<ggrid, 256>>>(a3p, w3[1], bk, kp);
    split3<<<MTOT, 256>>>(value, a3p, 1024, 2048);
    gemm_hmma<<<ggrid, 256>>>(a3p, w3[2], bv, vp);

    // transforms to per-head split layouts
    t_qk<<<MTOT, 256>>>(qp, q3p, 0.125f, 64, 128);   // q: [hi|lo|hi]
    t_qk<<<MTOT, 256>>>(kp, k3p, 1.0f, 128, 64);     // k: [hi|hi|lo]
    t_v<<<MTOT, 256>>>(vp, vhp, vlp);

    // attention -> a3 directly
    const int asmem = 131072;
    cudaFuncSetAttribute(attn_hmma, cudaFuncAttributeMaxDynamicSharedMemorySize, asmem);
    attn_hmma<<<dim3(SEQ / 128, NH, BATCH), 256, asmem>>>(q3p, k3p, vhp, vlp, a3p);

    // out projection
    gemm_hmma<<<ggrid, 256>>>(a3p, w3[3], bo, out);
}

// round 6
// speedup vs baseline: 3.0756x; 1.0293x over previous
#include <cuda_runtime.h>
#include <cuda_bf16.h>
#include <cstdint>
#include <cstddef>

#define BATCH 4
#define SEQ   2048
#define EMB   1024
#define NH    16
#define HD    64
#define MTOT  (BATCH * SEQ)        /* 8192 */
#define KSPLIT (3 * EMB)           /* 3072: W-side 3-block */
#define KA2   (2 * EMB)            /* 2048: A-side 2-block [hi|lo] */
#define BK    32
#define NITER (KSPLIT / BK)        /* 96 */
#define LOG2E 1.44269504f
#define NEG_BIG (-1e30f)
#define BHS   ((size_t)BATCH * NH * SEQ)   /* 131072 per-head rows */

// ---------------- scratch (__device__ globals; no allocs) -------------------
__device__ __align__(1024) __nv_bfloat16 g_a2[(size_t)MTOT * KA2];      // 32MB
__device__ __align__(1024) __nv_bfloat16 g_w3[4][(size_t)EMB * KSPLIT]; // 4x6MB
__device__ __align__(1024) __nv_bfloat16 g_q2[BHS * 128];  // [b,h,s][hi|lo] 32MB
__device__ __align__(1024) __nv_bfloat16 g_k2[BHS * 128];  // 32MB
__device__ __align__(1024) __nv_bfloat16 g_vh[BHS * HD];   // 16MB
__device__ __align__(1024) __nv_bfloat16 g_vl[BHS * HD];   // 16MB

// ---------------- PTX helpers (baseline ISA: sm_80-era ops) -----------------
__device__ __forceinline__ uint32_t smem_u32(const void* p) {
    uint32_t a;
    asm("{ .reg .u64 t; cvta.to.shared.u64 t, %1; cvt.u32.u64 %0, t; }" : "=r"(a) : "l"(p));
    return a;
}
#define CP_ASYNC16(dst, src) \
    asm volatile("cp.async.cg.shared.global [%0], [%1], 16;" :: "r"(dst), "l"(src) : "memory")
#define CP_COMMIT() asm volatile("cp.async.commit_group;" ::: "memory")
#define CP_WAIT1()  asm volatile("cp.async.wait_group 1;" ::: "memory")
#define CP_WAIT2()  asm volatile("cp.async.wait_group 2;" ::: "memory")

__device__ __forceinline__ void ldsm4(uint32_t (&r)[4], uint32_t addr) {
    asm volatile("ldmatrix.sync.aligned.m8n8.x4.shared.b16 {%0,%1,%2,%3}, [%4];"
                 : "=r"(r[0]), "=r"(r[1]), "=r"(r[2]), "=r"(r[3]) : "r"(addr));
}
__device__ __forceinline__ void ldsm4t(uint32_t (&r)[4], uint32_t addr) {
    asm volatile("ldmatrix.sync.aligned.m8n8.x4.trans.shared.b16 {%0,%1,%2,%3}, [%4];"
                 : "=r"(r[0]), "=r"(r[1]), "=r"(r[2]), "=r"(r[3]) : "r"(addr));
}
__device__ __forceinline__ void mma16816(float (&d)[4], const uint32_t (&a)[4],
                                         uint32_t b0, uint32_t b1) {
    asm volatile(
        "mma.sync.aligned.m16n8k16.row.col.f32.bf16.bf16.f32 "
        "{%0,%1,%2,%3}, {%4,%5,%6,%7}, {%8,%9}, {%0,%1,%2,%3};"
        : "+f"(d[0]), "+f"(d[1]), "+f"(d[2]), "+f"(d[3])
        : "r"(a[0]), "r"(a[1]), "r"(a[2]), "r"(a[3]), "r"(b0), "r"(b1));
}
__device__ __forceinline__ uint32_t pk2(__nv_bfloat16 a, __nv_bfloat16 b) {
    __nv_bfloat162 t = __halves2bfloat162(a, b);
    return *reinterpret_cast<uint32_t*>(&t);
}
__device__ __forceinline__ void split1(float v, __nv_bfloat16& h, __nv_bfloat16& l) {
    h = __float2bfloat16(v);
    l = __float2bfloat16(v - __bfloat162float(h));
}

// ---------------------------------------------------------------------------
// split3: fp32 -> bf16 hi/lo, 3 K-blocks (weights: [hi|hi|lo]).
// ---------------------------------------------------------------------------
__global__ __launch_bounds__(256)
void split3(const float* __restrict__ X, __nv_bfloat16* __restrict__ Y,
            int off_lo, int off_hi2)
{
    size_t idx = (size_t)blockIdx.x * 256 + threadIdx.x;
    size_t row = idx >> 8;
    int    c   = (int)(idx & 255) << 2;
    float4 x = ((const float4*)X)[idx];
    __nv_bfloat16 h0, h1, h2, h3, l0, l1, l2, l3;
    split1(x.x, h0, l0); split1(x.y, h1, l1);
    split1(x.z, h2, l2); split1(x.w, h3, l3);
    uint2 hv = make_uint2(pk2(h0, h1), pk2(h2, h3));
    uint2 lv = make_uint2(pk2(l0, l1), pk2(l2, l3));
    size_t base = row * (size_t)KSPLIT + c;
    *(uint2*)(Y + base)           = hv;
    *(uint2*)(Y + base + off_lo)  = lv;
    *(uint2*)(Y + base + off_hi2) = hv;
}

// split2: fp32 -> bf16 [hi|lo] (activations, 2048-wide rows)
__global__ __launch_bounds__(256)
void split2(const float* __restrict__ X, __nv_bfloat16* __restrict__ Y)
{
    size_t idx = (size_t)blockIdx.x * 256 + threadIdx.x;
    size_t row = idx >> 8;
    int    c   = (int)(idx & 255) << 2;
    float4 x = ((const float4*)X)[idx];
    __nv_bfloat16 h0, h1, h2, h3, l0, l1, l2, l3;
    split1(x.x, h0, l0); split1(x.y, h1, l1);
    split1(x.z, h2, l2); split1(x.w, h3, l3);
    size_t base = row * (size_t)KA2 + c;
    *(uint2*)(Y + base)        = make_uint2(pk2(h0, h1), pk2(h2, h3));
    *(uint2*)(Y + base + 1024) = make_uint2(pk2(l0, l1), pk2(l2, l3));
}

// ---------------------------------------------------------------------------
// bf16 HMMA GEMM:  C = A2[8192,2048(LUT->3072)] @ W3[1024,3072]^T + bias
// mode 0: Cf[row][col] fp32        (out projection -> d_out)
// mode 1/2: per-head [hi|lo] 128-wide (q2 with scale, k2)
// mode 3: vh/vl 64-wide
// ---------------------------------------------------------------------------
__device__ __forceinline__ int koffA(int it) { return (it < 64 ? it : it - 64) * BK; }

__global__ __launch_bounds__(256, 2)
void gemm_hmma(const __nv_bfloat16* __restrict__ A, const __nv_bfloat16* __restrict__ W,
               const float* __restrict__ bias, float* __restrict__ Cf,
               __nv_bfloat16* __restrict__ OH, __nv_bfloat16* __restrict__ OL,
               int mode, float scale)
{
    __shared__ __align__(1024) char smem_raw[3 * 16384];
    const uint32_t sbase = smem_u32(smem_raw);

    const int tid  = threadIdx.x;
    const int lane = tid & 31;
    const int wid  = tid >> 5;
    const int wm   = wid >> 2;
    const int wn   = wid & 3;
    const int m0   = blockIdx.y * 128;
    const int n0   = blockIdx.x * 128;

    const __nv_bfloat16* Ap = A + (size_t)m0 * KA2;
    const __nv_bfloat16* Wp = W + (size_t)n0 * KSPLIT;

    const int lrow = tid >> 2;
    const int lc   = tid & 3;

    const int arow  = wm * 64 + (lane & 15);
    const int akh   = lane >> 4;
    const int aswz  = (arow >> 1) & 3;
    const int brow  = wn * 32 + (lane & 7) + ((lane & 16) ? 8 : 0);
    const int bkh   = (lane >> 3) & 1;
    const int bswz  = (brow >> 1) & 3;

    float acc[4][4][4];
    #pragma unroll
    for (int i = 0; i < 4; i++)
        #pragma unroll
        for (int j = 0; j < 4; j++)
            #pragma unroll
            for (int k = 0; k < 4; k++) acc[i][j][k] = 0.f;

    #pragma unroll
    for (int s = 0; s < 3; s++) {
        uint32_t sA = sbase + s * 16384;
        uint32_t sB = sA + 8192;
        const __nv_bfloat16* ag = Ap + koffA(s) + lc * 8;
        const __nv_bfloat16* wg = Wp + (size_t)s * BK + lc * 8;
        #pragma unroll
        for (int h = 0; h < 2; h++) {
            int r  = lrow + h * 64;
            int cs = lc ^ ((r >> 1) & 3);
            CP_ASYNC16(sA + r * 64 + cs * 16, ag + (size_t)r * KA2);
            CP_ASYNC16(sB + r * 64 + cs * 16, wg + (size_t)r * KSPLIT);
        }
        CP_COMMIT();
    }

    int st = 0;
    for (int it = 0; it < NITER; it++) {
        CP_WAIT2();
        __syncthreads();

        const uint32_t sA = sbase + st * 16384;
        const uint32_t sB = sA + 8192;

        #pragma unroll
        for (int ks = 0; ks < 2; ks++) {
            uint32_t a[4][4];
            uint32_t b[4][2];
            const int ac = ((ks * 2 + akh) ^ aswz) * 16;
            const int bc = ((ks * 2 + bkh) ^ bswz) * 16;
            #pragma unroll
            for (int mi = 0; mi < 4; mi++)
                ldsm4(a[mi], sA + (arow + mi * 16) * 64 + ac);
            #pragma unroll
            for (int nj = 0; nj < 2; nj++) {
                uint32_t t4[4];
                ldsm4(t4, sB + (brow + nj * 16) * 64 + bc);
                b[nj * 2][0]     = t4[0]; b[nj * 2][1]     = t4[1];
                b[nj * 2 + 1][0] = t4[2]; b[nj * 2 + 1][1] = t4[3];
            }
            #pragma unroll
            for (int mi = 0; mi < 4; mi++)
                #pragma unroll
                for (int ni = 0; ni < 4; ni++)
                    mma16816(acc[mi][ni], a[mi], b[ni][0], b[ni][1]);
        }
        __syncthreads();

        if (it + 3 < NITER) {
            const __nv_bfloat16* ag = Ap + koffA(it + 3) + lc * 8;
            const __nv_bfloat16* wg = Wp + (size_t)(it + 3) * BK + lc * 8;
            #pragma unroll
            for (int h = 0; h < 2; h++) {
                int r  = lrow + h * 64;
                int cs = lc ^ ((r >> 1) & 3);
                CP_ASYNC16(sA + r * 64 + cs * 16, ag + (size_t)r * KA2);
                CP_ASYNC16(sB + r * 64 + cs * 16, wg + (size_t)r * KSPLIT);
            }
        }
        CP_COMMIT();
        st = (st == 2) ? 0 : st + 1;
    }

    // ---- epilogue ----
    const int trow = lane >> 2;
    const int tcol = (lane & 3) * 2;
    #pragma unroll
    for (int mi = 0; mi < 4; mi++) {
        const int row = m0 + wm * 64 + mi * 16 + trow;     // and row+8
        #pragma unroll
        for (int ni = 0; ni < 4; ni++) {
            const int col = n0 + wn * 32 + ni * 8 + tcol;
            const float b0 = __ldg(bias + col), b1 = __ldg(bias + col + 1);
            float v00 = acc[mi][ni][0] + b0, v01 = acc[mi][ni][1] + b1;
            float v10 = acc[mi][ni][2] + b0, v11 = acc[mi][ni][3] + b1;
            if (mode == 0) {
                *(float2*)(Cf + (size_t)row * EMB + col)       = make_float2(v00, v01);
                *(float2*)(Cf + (size_t)(row + 8) * EMB + col) = make_float2(v10, v11);
            } else {
                v00 *= scale; v01 *= scale; v10 *= scale; v11 *= scale;
                const int hh = col >> 6, d = col & 63;
                const size_t drow = ((size_t)((row >> 11) * NH + hh)) * SEQ + (row & 2047);
                __nv_bfloat16 h0, h1, h2, h3, l0, l1, l2, l3;
                split1(v00, h0, l0); split1(v01, h1, l1);
                split1(v10, h2, l2); split1(v11, h3, l3);
                if (mode == 3) {
                    *(uint32_t*)(OH + drow * HD + d)       = pk2(h0, h1);
                    *(uint32_t*)(OH + (drow + 8) * HD + d) = pk2(h2, h3);
                    *(uint32_t*)(OL + drow * HD + d)       = pk2(l0, l1);
                    *(uint32_t*)(OL + (drow + 8) * HD + d) = pk2(l2, l3);
                } else {
                    __nv_bfloat16* p0 = OH + drow * 128 + d;
                    __nv_bfloat16* p1 = OH + (drow + 8) * 128 + d;
                    *(uint32_t*)(p0)      = pk2(h0, h1);
                    *(uint32_t*)(p0 + 64) = pk2(l0, l1);
                    *(uint32_t*)(p1)      = pk2(h2, h3);
                    *(uint32_t*)(p1 + 64) = pk2(l2, l3);
                }
            }
        }
    }
}

// ---------------------------------------------------------------------------
// HMMA flash attention (causal), bf16 3-term via 2-block [hi|lo] operands.
// Block: 128 queries x 1 head, 8 warps. Key tiles of 64, double-buffered.
// smem: Q 32KB | K 2x16KB | V 2x16KB = 96KB  -> 2 CTAs/SM.
// Epilogue writes a2 [hi|lo] rows directly.
// ---------------------------------------------------------------------------
__global__ __launch_bounds__(256, 2)
void attn_hmma(const __nv_bfloat16* __restrict__ Q2, const __nv_bfloat16* __restrict__ K2,
               const __nv_bfloat16* __restrict__ VH, const __nv_bfloat16* __restrict__ VL,
               __nv_bfloat16* __restrict__ A2)
{
    extern __shared__ __align__(1024) char smr[];
    const uint32_t sb = smem_u32(smr);
    const uint32_t QS = sb;                 // 4 slabs * 8192B
    const uint32_t KS = sb + 32768;         // 2 stages * 16384 (4 slabs * 4096)
    const uint32_t VS = sb + 65536;         // 2 stages * 16384 (vh 8KB + vl 8KB)

    const int tid  = threadIdx.x;
    const int lane = tid & 31;
    const int wid  = tid >> 5;
    const int bx   = blockIdx.x;
    const int head = blockIdx.y;
    const int bz   = blockIdx.z;
    const int qb0  = bx * 128;
    const size_t bh = (size_t)(bz * NH + head);
    const int nkb  = 2 * bx + 2;

    const __nv_bfloat16* Qp = Q2 + (bh * SEQ + qb0) * 128;
    const __nv_bfloat16* Kp = K2 + bh * SEQ * 128;
    const __nv_bfloat16* VHp = VH + bh * SEQ * HD;
    const __nv_bfloat16* VLp = VL + bh * SEQ * HD;

    // ---- load Q (4 slabs) + stage 0 K/V ----
    {
        const int r1 = tid >> 2, lc = tid & 3;
        #pragma unroll
        for (int kc = 0; kc < 4; kc++)
            #pragma unroll
            for (int h = 0; h < 2; h++) {
                int r = r1 + h * 64;
                int cs = lc ^ ((r >> 1) & 3);
                CP_ASYNC16(QS + kc * 8192 + r * 64 + cs * 16,
                           Qp + (size_t)r * 128 + kc * 32 + lc * 8);
            }
        int cs = lc ^ ((r1 >> 1) & 3);
        #pragma unroll
        for (int kc = 0; kc < 4; kc++)
            CP_ASYNC16(KS + kc * 4096 + r1 * 64 + cs * 16,
                       Kp + (size_t)r1 * 128 + kc * 32 + lc * 8);
        const int vr = tid >> 3, vc = tid & 7;
        #pragma unroll
        for (int h = 0; h < 2; h++) {
            int r = vr + h * 32;
            int pc = vc ^ (r & 7);
            CP_ASYNC16(VS + r * 128 + pc * 16, VHp + (size_t)r * HD + vc * 8);
            CP_ASYNC16(VS + 8192 + r * 128 + pc * 16, VLp + (size_t)r * HD + vc * 8);
        }
        CP_COMMIT();
    }

    const int arow = wid * 16 + (lane & 15);
    const int akh  = lane >> 4;
    const int aswz = (arow >> 1) & 3;
    const int brow = (lane & 7) + ((lane & 16) ? 8 : 0);
    const int bkh  = (lane >> 3) & 1;
    const int bswz = (brow >> 1) & 3;
    const int vrow = (lane & 7) + 8 * ((lane >> 3) & 1);
    const int vchb = lane >> 4;
    const int vswz = lane & 7;

    float of[8][4];
    #pragma unroll
    for (int i = 0; i < 8; i++)
        #pragma unroll
        for (int j = 0; j < 4; j++) of[i][j] = 0.f;
    float mq[2] = { NEG_BIG, NEG_BIG };
    float lq[2] = { 0.f, 0.f };

    const int qrow0 = qb0 + wid * 16 + (lane >> 2);

    for (int kb = 0; kb < nkb; kb++) {
        const int st = kb & 1;
        const int kbase = kb * 64;

        if (kb + 1 < nkb) {
            const int nb = (kb + 1) * 64;
            const int s2 = st ^ 1;
            const int r1 = tid >> 2, lc = tid & 3;
            int cs = lc ^ ((r1 >> 1) & 3);
            #pragma unroll
            for (int kc = 0; kc < 4; kc++)
                CP_ASYNC16(KS + s2 * 16384 + kc * 4096 + r1 * 64 + cs * 16,
                           Kp + (size_t)(nb + r1) * 128 + kc * 32 + lc * 8);
            const int vr = tid >> 3, vc = tid & 7;
            #pragma unroll
            for (int h = 0; h < 2; h++) {
                int r = vr + h * 32;
                int pc = vc ^ (r & 7);
                CP_ASYNC16(VS + s2 * 16384 + r * 128 + pc * 16,
                           VHp + (size_t)(nb + r) * HD + vc * 8);
                CP_ASYNC16(VS + s2 * 16384 + 8192 + r * 128 + pc * 16,
                           VLp + (size_t)(nb + r) * HD + vc * 8);
            }
        }
        CP_COMMIT();
        CP_WAIT1();
        __syncthreads();

        // ---- S = 3-term QK^T via slab map: (qh,kh)(ql,kh)(qh,kl) ----
        float sf[8][4];
        #pragma unroll
        for (int i = 0; i < 8; i++)
            #pragma unroll
            for (int j = 0; j < 4; j++) sf[i][j] = 0.f;

        const uint32_t Kst = KS + st * 16384;
        const int qsel[6] = { 0, 1, 2, 3, 0, 1 };
        const int ksel[6] = { 0, 1, 0, 1, 2, 3 };
        #pragma unroll
        for (int t = 0; t < 6; t++) {
            #pragma unroll
            for (int ks = 0; ks < 2; ks++) {
                uint32_t a[4];
                ldsm4(a, QS + qsel[t] * 8192 + arow * 64 + (((ks * 2 + akh) ^ aswz) * 16));
                const int bc = ((ks * 2 + bkh) ^ bswz) * 16;
                #pragma unroll
                for (int np = 0; np < 4; np++) {
                    uint32_t t4[4];
                    ldsm4(t4, Kst + ksel[t] * 4096 + (np * 16 + brow) * 64 + bc);
                    mma16816(sf[2 * np],     a, t4[0], t4[1]);
                    mma16816(sf[2 * np + 1], a, t4[2], t4[3]);
                }
            }
        }

        if (kb >= nkb - 2) {
            #pragma unroll
            for (int nt = 0; nt < 8; nt++) {
                int col = kbase + nt * 8 + 2 * (lane & 3);
                if (col     > qrow0)     sf[nt][0] = NEG_BIG;
                if (col + 1 > qrow0)     sf[nt][1] = NEG_BIG;
                if (col     > qrow0 + 8) sf[nt][2] = NEG_BIG;
                if (col + 1 > qrow0 + 8) sf[nt][3] = NEG_BIG;
            }
        }

        #pragma unroll
        for (int h = 0; h < 2; h++) {
            float mloc = NEG_BIG;
            #pragma unroll
            for (int nt = 0; nt < 8; nt++)
                mloc = fmaxf(mloc, fmaxf(sf[nt][2 * h], sf[nt][2 * h + 1]));
            mloc = fmaxf(mloc, __shfl_xor_sync(0xffffffffu, mloc, 1));
            mloc = fmaxf(mloc, __shfl_xor_sync(0xffffffffu, mloc, 2));
            float mnew = fmaxf(mq[h], mloc);
            float corr = exp2f((mq[h] - mnew) * LOG2E);
            mq[h] = mnew;
            lq[h] *= corr;
            float ps = 0.f;
            #pragma unroll
            for (int nt = 0; nt < 8; nt++) {
                float p0 = exp2f((sf[nt][2 * h] - mnew) * LOG2E);
                float p1 = exp2f((sf[nt][2 * h + 1] - mnew) * LOG2E);
                sf[nt][2 * h] = p0; sf[nt][2 * h + 1] = p1;
                ps += p0 + p1;
                of[nt][2 * h] *= corr; of[nt][2 * h + 1] *= corr;
            }
            ps += __shfl_xor_sync(0xffffffffu, ps, 1);
            ps += __shfl_xor_sync(0xffffffffu, ps, 2);
            lq[h] += ps;
        }

        // ---- O += P.V (ph*vh + pl*vh + ph*vl) ----
        const uint32_t Vst = VS + st * 16384;
        #pragma unroll
        for (int kc2 = 0; kc2 < 4; kc2++) {
            const int j0 = 2 * kc2, j1 = j0 + 1;
            uint32_t ph[4], pl[4];
            #pragma unroll
            for (int q = 0; q < 4; q++) {
                const float p0 = (q & 2) ? sf[j1][(q & 1) * 2]     : sf[j0][(q & 1) * 2];
                const float p1 = (q & 2) ? sf[j1][(q & 1) * 2 + 1] : sf[j0][(q & 1) * 2 + 1];
                __nv_bfloat16 h0, h1, l0, l1;
                split1(p0, h0, l0); split1(p1, h1, l1);
                ph[q] = pk2(h0, h1);
                pl[q] = pk2(l0, l1);
            }
            const uint32_t rowoff = (kc2 * 16 + vrow) * 128;
            #pragma unroll
            for (int np = 0; np < 4; np++) {
                const int pc = (2 * np + vchb) ^ vswz;
                uint32_t bh4[4], bl4[4];
                ldsm4t(bh4, Vst + rowoff + pc * 16);
                ldsm4t(bl4, Vst + 8192 + rowoff + pc * 16);
                mma16816(of[2 * np],     ph, bh4[0], bh4[1]);
                mma16816(of[2 * np + 1], ph, bh4[2], bh4[3]);
                mma16816(of[2 * np],     pl, bh4[0], bh4[1]);
                mma16816(of[2 * np + 1], pl, bh4[2], bh4[3]);
                mma16816(of[2 * np],     ph, bl4[0], bl4[1]);
                mma16816(of[2 * np + 1], ph, bl4[2], bl4[3]);
            }
        }
        __syncthreads();
    }

    // ---- epilogue: normalize, split, write a2 [hi|lo] ----
    const float inv0 = 1.f / lq[0];
    const float inv1 = 1.f / lq[1];
    const size_t ar0 = (size_t)bz * SEQ + qb0 + wid * 16 + (lane >> 2);
    const size_t ar1 = ar0 + 8;
    const int colb = head * 64 + 2 * (lane & 3);
    #pragma unroll
    for (int nt = 0; nt < 8; nt++) {
        int col = colb + nt * 8;
        float v0 = of[nt][0] * inv0, v1 = of[nt][1] * inv0;
        float v2 = of[nt][2] * inv1, v3 = of[nt][3] * inv1;
        __nv_bfloat16 h0, h1, h2, h3, l0, l1, l2, l3;
        split1(v0, h0, l0); split1(v1, h1, l1);
        split1(v2, h2, l2); split1(v3, h3, l3);
        __nv_bfloat16* d0 = A2 + ar0 * KA2 + col;
        __nv_bfloat16* d1 = A2 + ar1 * KA2 + col;
        *(uint32_t*)(d0)        = pk2(h0, h1);
        *(uint32_t*)(d0 + 1024) = pk2(l0, l1);
        *(uint32_t*)(d1)        = pk2(h2, h3);
        *(uint32_t*)(d1 + 1024) = pk2(l2, l3);
    }
}

// ---------------------------------------------------------------------------
extern "C" void kernel_launch(void* const* d_in, const int* in_sizes, int n_in,
                              void* d_out, int out_size)
{
    const float* query = (const float*)d_in[0];
    const float* key   = (const float*)d_in[1];
    const float* value = (const float*)d_in[2];
    const float* Wq = (const float*)d_in[4];  const float* bq = (const float*)d_in[5];
    const float* Wk = (const float*)d_in[6];  const float* bk = (const float*)d_in[7];
    const float* Wv = (const float*)d_in[8];  const float* bv = (const float*)d_in[9];
    const float* Wo = (const float*)d_in[10]; const float* bo = (const float*)d_in[11];
    float* out = (float*)d_out;

    __nv_bfloat16 *a2p, *w3p, *q2p, *k2p, *vhp, *vlp;
    cudaGetSymbolAddress((void**)&a2p, g_a2);
    cudaGetSymbolAddress((void**)&w3p, g_w3);
    cudaGetSymbolAddress((void**)&q2p, g_q2);
    cudaGetSymbolAddress((void**)&k2p, g_k2);
    cudaGetSymbolAddress((void**)&vhp, g_vh);
    cudaGetSymbolAddress((void**)&vlp, g_vl);

    __nv_bfloat16* w3[4] = { w3p,
                             w3p + (size_t)EMB * KSPLIT,
                             w3p + 2 * (size_t)EMB * KSPLIT,
                             w3p + 3 * (size_t)EMB * KSPLIT };

    dim3 ggrid(EMB / 128, MTOT / 128);

    // weights -> [hi | hi | lo]
    split3<<<EMB, 256>>>(Wq, w3[0], 2048, 1024);
    split3<<<EMB, 256>>>(Wk, w3[1], 2048, 1024);
    split3<<<EMB, 256>>>(Wv, w3[2], 2048, 1024);
    split3<<<EMB, 256>>>(Wo, w3[3], 2048, 1024);

    // projections with fused per-head split epilogues
    split2<<<MTOT, 256>>>(query, a2p);
    gemm_hmma<<<ggrid, 256>>>(a2p, w3[0], bq, nullptr, q2p, nullptr, 1, 0.125f);
    split2<<<MTOT, 256>>>(key, a2p);
    gemm_hmma<<<ggrid, 256>>>(a2p, w3[1], bk, nullptr, k2p, nullptr, 2, 1.0f);
    split2<<<MTOT, 256>>>(value, a2p);
    gemm_hmma<<<ggrid, 256>>>(a2p, w3[2], bv, nullptr, vhp, vlp, 3, 1.0f);

    // attention -> a2 directly
    const int asmem = 98304;
    cudaFuncSetAttribute(attn_hmma, cudaFuncAttributeMaxDynamicSharedMemorySize, asmem);
    attn_hmma<<<dim3(SEQ / 128, NH, BATCH), 256, asmem>>>(q2p, k2p, vhp, vlp, a2p);

    // out projection -> d_out
    gemm_hmma<<<ggrid, 256>>>(a2p, w3[3], bo, out, nullptr, nullptr, 0, 1.0f);
}

// round 7
// speedup vs baseline: 3.3763x; 1.0977x over previous
#include <cuda_runtime.h>
#include <cuda_bf16.h>
#include <cstdint>
#include <cstddef>

#define BATCH 4
#define SEQ   2048
#define EMB   1024
#define NH    16
#define HD    64
#define MTOT  (BATCH * SEQ)        /* 8192 */
#define KSPLIT (3 * EMB)           /* 3072: W-side 3-block */
#define KA2   (2 * EMB)            /* 2048: A-side 2-block [hi|lo] */
#define BK    32
#define NITER (KSPLIT / BK)        /* 96 */
#define LOG2E 1.44269504f
#define NEG_BIG (-1e30f)
#define BHS   ((size_t)BATCH * NH * SEQ)   /* 131072 per-head rows */

// ---------------- scratch (__device__ globals; no allocs) -------------------
__device__ __align__(1024) __nv_bfloat16 g_a2[3][(size_t)MTOT * KA2];   // 3x32MB
__device__ __align__(1024) __nv_bfloat16 g_w3[4][(size_t)EMB * KSPLIT]; // 4x6MB
__device__ __align__(1024) __nv_bfloat16 g_q2[BHS * 128];  // [b,h,s][hi|lo] 32MB
__device__ __align__(1024) __nv_bfloat16 g_k2[BHS * 128];  // 32MB
__device__ __align__(1024) __nv_bfloat16 g_vh[BHS * HD];   // 16MB
__device__ __align__(1024) __nv_bfloat16 g_vl[BHS * HD];   // 16MB

// ---------------- PTX helpers (baseline ISA: sm_80-era ops) -----------------
__device__ __forceinline__ uint32_t smem_u32(const void* p) {
    uint32_t a;
    asm("{ .reg .u64 t; cvta.to.shared.u64 t, %1; cvt.u32.u64 %0, t; }" : "=r"(a) : "l"(p));
    return a;
}
#define CP_ASYNC16(dst, src) \
    asm volatile("cp.async.cg.shared.global [%0], [%1], 16;" :: "r"(dst), "l"(src) : "memory")
#define CP_COMMIT() asm volatile("cp.async.commit_group;" ::: "memory")
#define CP_WAIT1()  asm volatile("cp.async.wait_group 1;" ::: "memory")
#define CP_WAIT2()  asm volatile("cp.async.wait_group 2;" ::: "memory")

__device__ __forceinline__ void ldsm4(uint32_t (&r)[4], uint32_t addr) {
    asm volatile("ldmatrix.sync.aligned.m8n8.x4.shared.b16 {%0,%1,%2,%3}, [%4];"
                 : "=r"(r[0]), "=r"(r[1]), "=r"(r[2]), "=r"(r[3]) : "r"(addr));
}
__device__ __forceinline__ void ldsm4t(uint32_t (&r)[4], uint32_t addr) {
    asm volatile("ldmatrix.sync.aligned.m8n8.x4.trans.shared.b16 {%0,%1,%2,%3}, [%4];"
                 : "=r"(r[0]), "=r"(r[1]), "=r"(r[2]), "=r"(r[3]) : "r"(addr));
}
__device__ __forceinline__ void mma16816(float (&d)[4], const uint32_t (&a)[4],
                                         uint32_t b0, uint32_t b1) {
    asm volatile(
        "mma.sync.aligned.m16n8k16.row.col.f32.bf16.bf16.f32 "
        "{%0,%1,%2,%3}, {%4,%5,%6,%7}, {%8,%9}, {%0,%1,%2,%3};"
        : "+f"(d[0]), "+f"(d[1]), "+f"(d[2]), "+f"(d[3])
        : "r"(a[0]), "r"(a[1]), "r"(a[2]), "r"(a[3]), "r"(b0), "r"(b1));
}
__device__ __forceinline__ uint32_t pk2(__nv_bfloat16 a, __nv_bfloat16 b) {
    __nv_bfloat162 t = __halves2bfloat162(a, b);
    return *reinterpret_cast<uint32_t*>(&t);
}
__device__ __forceinline__ void split1(float v, __nv_bfloat16& h, __nv_bfloat16& l) {
    h = __float2bfloat16(v);
    l = __float2bfloat16(v - __bfloat162float(h));
}

// ---------------------------------------------------------------------------
// split3: weights fp32 -> bf16 [hi|hi|lo] (3 K-blocks)
// ---------------------------------------------------------------------------
__global__ __launch_bounds__(256)
void split3(const float* __restrict__ X, __nv_bfloat16* __restrict__ Y,
            int off_lo, int off_hi2)
{
    size_t idx = (size_t)blockIdx.x * 256 + threadIdx.x;
    size_t row = idx >> 8;
    int    c   = (int)(idx & 255) << 2;
    float4 x = ((const float4*)X)[idx];
    __nv_bfloat16 h0, h1, h2, h3, l0, l1, l2, l3;
    split1(x.x, h0, l0); split1(x.y, h1, l1);
    split1(x.z, h2, l2); split1(x.w, h3, l3);
    uint2 hv = make_uint2(pk2(h0, h1), pk2(h2, h3));
    uint2 lv = make_uint2(pk2(l0, l1), pk2(l2, l3));
    size_t base = row * (size_t)KSPLIT + c;
    *(uint2*)(Y + base)           = hv;
    *(uint2*)(Y + base + off_lo)  = lv;
    *(uint2*)(Y + base + off_hi2) = hv;
}

// split2 (z-batched): activations fp32 -> bf16 [hi|lo], z = which input
__global__ __launch_bounds__(256)
void split2(const float* __restrict__ X0, const float* __restrict__ X1,
            const float* __restrict__ X2, __nv_bfloat16* __restrict__ Y)
{
    const int z = blockIdx.y;
    const float* X = (z == 0) ? X0 : (z == 1) ? X1 : X2;
    size_t idx = (size_t)blockIdx.x * 256 + threadIdx.x;
    size_t row = idx >> 8;
    int    c   = (int)(idx & 255) << 2;
    float4 x = ((const float4*)X)[idx];
    __nv_bfloat16 h0, h1, h2, h3, l0, l1, l2, l3;
    split1(x.x, h0, l0); split1(x.y, h1, l1);
    split1(x.z, h2, l2); split1(x.w, h3, l3);
    size_t base = (size_t)z * MTOT * KA2 + row * (size_t)KA2 + c;
    *(uint2*)(Y + base)        = make_uint2(pk2(h0, h1), pk2(h2, h3));
    *(uint2*)(Y + base + 1024) = make_uint2(pk2(l0, l1), pk2(l2, l3));
}

// ---------------------------------------------------------------------------
// GEMM core:  C = A2[*,2048(LUT->3072)] @ W3[*,3072]^T + bias
// 4-stage cp.async pipeline, ONE __syncthreads per k-iter.
// mode 0: fp32 out; 1/2: per-head [hi|lo] (q2 scaled, k2); 3: vh/vl.
// ---------------------------------------------------------------------------
__device__ __forceinline__ int koffA(int it) { return (it < 64 ? it : it - 64) * BK; }

__device__ __forceinline__ void gemm_core(
    const __nv_bfloat16* __restrict__ A, const __nv_bfloat16* __restrict__ W,
    const float* __restrict__ bias, float* __restrict__ Cf,
    __nv_bfloat16* __restrict__ OH, __nv_bfloat16* __restrict__ OL,
    int mode, float scale, int m0, int n0, char* smem_raw)
{
    const uint32_t sbase = smem_u32(smem_raw);

    const int tid  = threadIdx.x;
    const int lane = tid & 31;
    const int wid  = tid >> 5;
    const int wm   = wid >> 2;
    const int wn   = wid & 3;

    const __nv_bfloat16* Ap = A + (size_t)m0 * KA2;
    const __nv_bfloat16* Wp = W + (size_t)n0 * KSPLIT;

    const int lrow = tid >> 2;
    const int lc   = tid & 3;

    const int arow  = wm * 64 + (lane & 15);
    const int akh   = lane >> 4;
    const int aswz  = (arow >> 1) & 3;
    const int brow  = wn * 32 + (lane & 7) + ((lane & 16) ? 8 : 0);
    const int bkh   = (lane >> 3) & 1;
    const int bswz  = (brow >> 1) & 3;

    float acc[4][4][4];
    #pragma unroll
    for (int i = 0; i < 4; i++)
        #pragma unroll
        for (int j = 0; j < 4; j++)
            #pragma unroll
            for (int k = 0; k < 4; k++) acc[i][j][k] = 0.f;

    #pragma unroll
    for (int s = 0; s < 3; s++) {
        uint32_t sA = sbase + s * 16384;
        uint32_t sB = sA + 8192;
        const __nv_bfloat16* ag = Ap + koffA(s) + lc * 8;
        const __nv_bfloat16* wg = Wp + (size_t)s * BK + lc * 8;
        #pragma unroll
        for (int h = 0; h < 2; h++) {
            int r  = lrow + h * 64;
            int cs = lc ^ ((r >> 1) & 3);
            CP_ASYNC16(sA + r * 64 + cs * 16, ag + (size_t)r * KA2);
            CP_ASYNC16(sB + r * 64 + cs * 16, wg + (size_t)r * KSPLIT);
        }
        CP_COMMIT();
    }

    for (int it = 0; it < NITER; it++) {
        CP_WAIT2();
        __syncthreads();

        const int st = it & 3;
        const uint32_t sA = sbase + st * 16384;
        const uint32_t sB = sA + 8192;

        #pragma unroll
        for (int ks = 0; ks < 2; ks++) {
            uint32_t a[4][4];
            uint32_t b[4][2];
            const int ac = ((ks * 2 + akh) ^ aswz) * 16;
            const int bc = ((ks * 2 + bkh) ^ bswz) * 16;
            #pragma unroll
            for (int mi = 0; mi < 4; mi++)
                ldsm4(a[mi], sA + (arow + mi * 16) * 64 + ac);
            #pragma unroll
            for (int nj = 0; nj < 2; nj++) {
                uint32_t t4[4];
                ldsm4(t4, sB + (brow + nj * 16) * 64 + bc);
                b[nj * 2][0]     = t4[0]; b[nj * 2][1]     = t4[1];
                b[nj * 2 + 1][0] = t4[2]; b[nj * 2 + 1][1] = t4[3];
            }
            #pragma unroll
            for (int mi = 0; mi < 4; mi++)
                #pragma unroll
                for (int ni = 0; ni < 4; ni++)
                    mma16816(acc[mi][ni], a[mi], b[ni][0], b[ni][1]);
        }

        // 4 stages: (it+3)&3 != it&3, and top-of-iter sync ordered all warps
        // past compute of it-1 (the previous occupant) -> no WAR, no 2nd sync.
        if (it + 3 < NITER) {
            const int s2 = (it + 3) & 3;
            const uint32_t dA = sbase + s2 * 16384;
            const uint32_t dB = dA + 8192;
            const __nv_bfloat16* ag = Ap + koffA(it + 3) + lc * 8;
            const __nv_bfloat16* wg = Wp + (size_t)(it + 3) * BK + lc * 8;
            #pragma unroll
            for (int h = 0; h < 2; h++) {
                int r  = lrow + h * 64;
                int cs = lc ^ ((r >> 1) & 3);
                CP_ASYNC16(dA + r * 64 + cs * 16, ag + (size_t)r * KA2);
                CP_ASYNC16(dB + r * 64 + cs * 16, wg + (size_t)r * KSPLIT);
            }
        }
        CP_COMMIT();
    }

    // ---- epilogue ----
    const int trow = lane >> 2;
    const int tcol = (lane & 3) * 2;
    #pragma unroll
    for (int mi = 0; mi < 4; mi++) {
        const int row = m0 + wm * 64 + mi * 16 + trow;
        #pragma unroll
        for (int ni = 0; ni < 4; ni++) {
            const int col = n0 + wn * 32 + ni * 8 + tcol;
            const float b0 = __ldg(bias + col), b1 = __ldg(bias + col + 1);
            float v00 = acc[mi][ni][0] + b0, v01 = acc[mi][ni][1] + b1;
            float v10 = acc[mi][ni][2] + b0, v11 = acc[mi][ni][3] + b1;
            if (mode == 0) {
                *(float2*)(Cf + (size_t)row * EMB + col)       = make_float2(v00, v01);
                *(float2*)(Cf + (size_t)(row + 8) * EMB + col) = make_float2(v10, v11);
            } else {
                v00 *= scale; v01 *= scale; v10 *= scale; v11 *= scale;
                const int hh = col >> 6, d = col & 63;
                const size_t drow = ((size_t)((row >> 11) * NH + hh)) * SEQ + (row & 2047);
                __nv_bfloat16 h0, h1, h2, h3, l0, l1, l2, l3;
                split1(v00, h0, l0); split1(v01, h1, l1);
                split1(v10, h2, l2); split1(v11, h3, l3);
                if (mode == 3) {
                    *(uint32_t*)(OH + drow * HD + d)       = pk2(h0, h1);
                    *(uint32_t*)(OH + (drow + 8) * HD + d) = pk2(h2, h3);
                    *(uint32_t*)(OL + drow * HD + d)       = pk2(l0, l1);
                    *(uint32_t*)(OL + (drow + 8) * HD + d) = pk2(l2, l3);
                } else {
                    __nv_bfloat16* p0 = OH + drow * 128 + d;
                    __nv_bfloat16* p1 = OH + (drow + 8) * 128 + d;
                    *(uint32_t*)(p0)      = pk2(h0, h1);
                    *(uint32_t*)(p0 + 64) = pk2(l0, l1);
                    *(uint32_t*)(p1)      = pk2(h2, h3);
                    *(uint32_t*)(p1 + 64) = pk2(l2, l3);
                }
            }
        }
    }
}

// z-batched QKV projections: z=0 -> q2 (scaled), z=1 -> k2, z=2 -> vh/vl
__global__ __launch_bounds__(256, 2)
void gemm_qkv(const __nv_bfloat16* __restrict__ Abase,
              const __nv_bfloat16* __restrict__ Wbase,
              const float* __restrict__ bq, const float* __restrict__ bk,
              const float* __restrict__ bv,
              __nv_bfloat16* __restrict__ q2, __nv_bfloat16* __restrict__ k2,
              __nv_bfloat16* __restrict__ vh, __nv_bfloat16* __restrict__ vl)
{
    extern __shared__ __align__(1024) char smem_raw[];
    const int z = blockIdx.z;
    const __nv_bfloat16* A = Abase + (size_t)z * MTOT * KA2;
    const __nv_bfloat16* W = Wbase + (size_t)z * EMB * KSPLIT;
    const float* bias = (z == 0) ? bq : (z == 1) ? bk : bv;
    __nv_bfloat16* OH = (z == 0) ? q2 : (z == 1) ? k2 : vh;
    __nv_bfloat16* OL = (z == 2) ? vl : nullptr;
    const float scale = (z == 0) ? 0.125f : 1.0f;
    gemm_core(A, W, bias, nullptr, OH, OL, z + 1, scale,
              blockIdx.y * 128, blockIdx.x * 128, smem_raw);
}

// out projection -> fp32 d_out
__global__ __launch_bounds__(256, 2)
void gemm_out(const __nv_bfloat16* __restrict__ A, const __nv_bfloat16* __restrict__ W,
              const float* __restrict__ bias, float* __restrict__ Cf)
{
    extern __shared__ __align__(1024) char smem_raw[];
    gemm_core(A, W, bias, Cf, nullptr, nullptr, 0, 1.0f,
              blockIdx.y * 128, blockIdx.x * 128, smem_raw);
}

// ---------------------------------------------------------------------------
// HMMA flash attention (causal), bf16 3-term via 2-block [hi|lo] operands.
// Block: 128 queries x 1 head, 8 warps, 64-key tiles, double-buffered.
// LPT: heaviest blocks (largest bx) launch first via reversed blockIdx.x.
// ---------------------------------------------------------------------------
__global__ __launch_bounds__(256, 2)
void attn_hmma(const __nv_bfloat16* __restrict__ Q2, const __nv_bfloat16* __restrict__ K2,
               const __nv_bfloat16* __restrict__ VH, const __nv_bfloat16* __restrict__ VL,
               __nv_bfloat16* __restrict__ A2)
{
    extern __shared__ __align__(1024) char smr[];
    const uint32_t sb = smem_u32(smr);
    const uint32_t QS = sb;                 // 4 slabs * 8192B
    const uint32_t KS = sb + 32768;         // 2 stages * 16384
    const uint32_t VS = sb + 65536;         // 2 stages * 16384

    const int tid  = threadIdx.x;
    const int lane = tid & 31;
    const int wid  = tid >> 5;
    const int bx   = gridDim.x - 1 - blockIdx.x;   // LPT: heavy first
    const int head = blockIdx.y;
    const int bz   = blockIdx.z;
    const int qb0  = bx * 128;
    const size_t bh = (size_t)(bz * NH + head);
    const int nkb  = 2 * bx + 2;

    const __nv_bfloat16* Qp = Q2 + (bh * SEQ + qb0) * 128;
    const __nv_bfloat16* Kp = K2 + bh * SEQ * 128;
    const __nv_bfloat16* VHp = VH + bh * SEQ * HD;
    const __nv_bfloat16* VLp = VL + bh * SEQ * HD;

    {
        const int r1 = tid >> 2, lc = tid & 3;
        #pragma unroll
        for (int kc = 0; kc < 4; kc++)
            #pragma unroll
            for (int h = 0; h < 2; h++) {
                int r = r1 + h * 64;
                int cs = lc ^ ((r >> 1) & 3);
                CP_ASYNC16(QS + kc * 8192 + r * 64 + cs * 16,
                           Qp + (size_t)r * 128 + kc * 32 + lc * 8);
            }
        int cs = lc ^ ((r1 >> 1) & 3);
        #pragma unroll
        for (int kc = 0; kc < 4; kc++)
            CP_ASYNC16(KS + kc * 4096 + r1 * 64 + cs * 16,
                       Kp + (size_t)r1 * 128 + kc * 32 + lc * 8);
        const int vr = tid >> 3, vc = tid & 7;
        #pragma unroll
        for (int h = 0; h < 2; h++) {
            int r = vr + h * 32;
            int pc = vc ^ (r & 7);
            CP_ASYNC16(VS + r * 128 + pc * 16, VHp + (size_t)r * HD + vc * 8);
            CP_ASYNC16(VS + 8192 + r * 128 + pc * 16, VLp + (size_t)r * HD + vc * 8);
        }
        CP_COMMIT();
    }

    const int arow = wid * 16 + (lane & 15);
    const int akh  = lane >> 4;
    const int aswz = (arow >> 1) & 3;
    const int brow = (lane & 7) + ((lane & 16) ? 8 : 0);
    const int bkh  = (lane >> 3) & 1;
    const int bswz = (brow >> 1) & 3;
    const int vrow = (lane & 7) + 8 * ((lane >> 3) & 1);
    const int vchb = lane >> 4;
    const int vswz = lane & 7;

    float of[8][4];
    #pragma unroll
    for (int i = 0; i < 8; i++)
        #pragma unroll
        for (int j = 0; j < 4; j++) of[i][j] = 0.f;
    float mq[2] = { NEG_BIG, NEG_BIG };
    float lq[2] = { 0.f, 0.f };

    const int qrow0 = qb0 + wid * 16 + (lane >> 2);

    for (int kb = 0; kb < nkb; kb++) {
        const int st = kb & 1;
        const int kbase = kb * 64;

        if (kb + 1 < nkb) {
            const int nb = (kb + 1) * 64;
            const int s2 = st ^ 1;
            const int r1 = tid >> 2, lc = tid & 3;
            int cs = lc ^ ((r1 >> 1) & 3);
            #pragma unroll
            for (int kc = 0; kc < 4; kc++)
                CP_ASYNC16(KS + s2 * 16384 + kc * 4096 + r1 * 64 + cs * 16,
                           Kp + (size_t)(nb + r1) * 128 + kc * 32 + lc * 8);
            const int vr = tid >> 3, vc = tid & 7;
            #pragma unroll
            for (int h = 0; h < 2; h++) {
                int r = vr + h * 32;
                int pc = vc ^ (r & 7);
                CP_ASYNC16(VS + s2 * 16384 + r * 128 + pc * 16,
                           VHp + (size_t)(nb + r) * HD + vc * 8);
                CP_ASYNC16(VS + s2 * 16384 + 8192 + r * 128 + pc * 16,
                           VLp + (size_t)(nb + r) * HD + vc * 8);
            }
        }
        CP_COMMIT();
        CP_WAIT1();
        __syncthreads();

        float sf[8][4];
        #pragma unroll
        for (int i = 0; i < 8; i++)
            #pragma unroll
            for (int j = 0; j < 4; j++) sf[i][j] = 0.f;

        const uint32_t Kst = KS + st * 16384;
        const int qsel[6] = { 0, 1, 2, 3, 0, 1 };
        const int ksel[6] = { 0, 1, 0, 1, 2, 3 };
        #pragma unroll
        for (int t = 0; t < 6; t++) {
            #pragma unroll
            for (int ks = 0; ks < 2; ks++) {
                uint32_t a[4];
                ldsm4(a, QS + qsel[t] * 8192 + arow * 64 + (((ks * 2 + akh) ^ aswz) * 16));
                const int bc = ((ks * 2 + bkh) ^ bswz) * 16;
                #pragma unroll
                for (int np = 0; np < 4; np++) {
                    uint32_t t4[4];
                    ldsm4(t4, Kst + ksel[t] * 4096 + (np * 16 + brow) * 64 + bc);
                    mma16816(sf[2 * np],     a, t4[0], t4[1]);
                    mma16816(sf[2 * np + 1], a, t4[2], t4[3]);
                }
            }
        }

        if (kb >= nkb - 2) {
            #pragma unroll
            for (int nt = 0; nt < 8; nt++) {
                int col = kbase + nt * 8 + 2 * (lane & 3);
                if (col     > qrow0)     sf[nt][0] = NEG_BIG;
                if (col + 1 > qrow0)     sf[nt][1] = NEG_BIG;
                if (col     > qrow0 + 8) sf[nt][2] = NEG_BIG;
                if (col + 1 > qrow0 + 8) sf[nt][3] = NEG_BIG;
            }
        }

        #pragma unroll
        for (int h = 0; h < 2; h++) {
            float mloc = NEG_BIG;
            #pragma unroll
            for (int nt = 0; nt < 8; nt++)
                mloc = fmaxf(mloc, fmaxf(sf[nt][2 * h], sf[nt][2 * h + 1]));
            mloc = fmaxf(mloc, __shfl_xor_sync(0xffffffffu, mloc, 1));
            mloc = fmaxf(mloc, __shfl_xor_sync(0xffffffffu, mloc, 2));
            float mnew = fmaxf(mq[h], mloc);
            float corr = exp2f((mq[h] - mnew) * LOG2E);
            mq[h] = mnew;
            lq[h] *= corr;
            float ps = 0.f;
            #pragma unroll
            for (int nt = 0; nt < 8; nt++) {
                float p0 = exp2f((sf[nt][2 * h] - mnew) * LOG2E);
                float p1 = exp2f((sf[nt][2 * h + 1] - mnew) * LOG2E);
                sf[nt][2 * h] = p0; sf[nt][2 * h + 1] = p1;
                ps += p0 + p1;
                of[nt][2 * h] *= corr; of[nt][2 * h + 1] *= corr;
            }
            ps += __shfl_xor_sync(0xffffffffu, ps, 1);
            ps += __shfl_xor_sync(0xffffffffu, ps, 2);
            lq[h] += ps;
        }

        const uint32_t Vst = VS + st * 16384;
        #pragma unroll
        for (int kc2 = 0; kc2 < 4; kc2++) {
            const int j0 = 2 * kc2, j1 = j0 + 1;
            uint32_t ph[4], pl[4];
            #pragma unroll
            for (int q = 0; q < 4; q++) {
                const float p0 = (q & 2) ? sf[j1][(q & 1) * 2]     : sf[j0][(q & 1) * 2];
                const float p1 = (q & 2) ? sf[j1][(q & 1) * 2 + 1] : sf[j0][(q & 1) * 2 + 1];
                __nv_bfloat16 h0, h1, l0, l1;
                split1(p0, h0, l0); split1(p1, h1, l1);
                ph[q] = pk2(h0, h1);
                pl[q] = pk2(l0, l1);
            }
            const uint32_t rowoff = (kc2 * 16 + vrow) * 128;
            #pragma unroll
            for (int np = 0; np < 4; np++) {
                const int pc = (2 * np + vchb) ^ vswz;
                uint32_t bh4[4], bl4[4];
                ldsm4t(bh4, Vst + rowoff + pc * 16);
                ldsm4t(bl4, Vst + 8192 + rowoff + pc * 16);
                mma16816(of[2 * np],     ph, bh4[0], bh4[1]);
                mma16816(of[2 * np + 1], ph, bh4[2], bh4[3]);
                mma16816(of[2 * np],     pl, bh4[0], bh4[1]);
                mma16816(of[2 * np + 1], pl, bh4[2], bh4[3]);
                mma16816(of[2 * np],     ph, bl4[0], bl4[1]);
                mma16816(of[2 * np + 1], ph, bl4[2], bl4[3]);
            }
        }
        __syncthreads();
    }

    const float inv0 = 1.f / lq[0];
    const float inv1 = 1.f / lq[1];
    const size_t ar0 = (size_t)bz * SEQ + qb0 + wid * 16 + (lane >> 2);
    const size_t ar1 = ar0 + 8;
    const int colb = head * 64 + 2 * (lane & 3);
    #pragma unroll
    for (int nt = 0; nt < 8; nt++) {
        int col = colb + nt * 8;
        float v0 = of[nt][0] * inv0, v1 = of[nt][1] * inv0;
        float v2 = of[nt][2] * inv1, v3 = of[nt][3] * inv1;
        __nv_bfloat16 h0, h1, h2, h3, l0, l1, l2, l3;
        split1(v0, h0, l0); split1(v1, h1, l1);
        split1(v2, h2, l2); split1(v3, h3, l3);
        __nv_bfloat16* d0 = A2 + ar0 * KA2 + col;
        __nv_bfloat16* d1 = A2 + ar1 * KA2 + col;
        *(uint32_t*)(d0)        = pk2(h0, h1);
        *(uint32_t*)(d0 + 1024) = pk2(l0, l1);
        *(uint32_t*)(d1)        = pk2(h2, h3);
        *(uint32_t*)(d1 + 1024) = pk2(l2, l3);
    }
}

// ---------------------------------------------------------------------------
extern "C" void kernel_launch(void* const* d_in, const int* in_sizes, int n_in,
                              void* d_out, int out_size)
{
    const float* query = (const float*)d_in[0];
    const float* key   = (const float*)d_in[1];
    const float* value = (const float*)d_in[2];
    const float* Wq = (const float*)d_in[4];  const float* bq = (const float*)d_in[5];
    const float* Wk = (const float*)d_in[6];  const float* bk = (const float*)d_in[7];
    const float* Wv = (const float*)d_in[8];  const float* bv = (const float*)d_in[9];
    const float* Wo = (const float*)d_in[10]; const float* bo = (const float*)d_in[11];
    float* out = (float*)d_out;

    __nv_bfloat16 *a2p, *w3p, *q2p, *k2p, *vhp, *vlp;
    cudaGetSymbolAddress((void**)&a2p, g_a2);
    cudaGetSymbolAddress((void**)&w3p, g_w3);
    cudaGetSymbolAddress((void**)&q2p, g_q2);
    cudaGetSymbolAddress((void**)&k2p, g_k2);
    cudaGetSymbolAddress((void**)&vhp, g_vh);
    cudaGetSymbolAddress((void**)&vlp, g_vl);

    const int gsm = 4 * 16384;   // 64KB dynamic
    cudaFuncSetAttribute(gemm_qkv, cudaFuncAttributeMaxDynamicSharedMemorySize, gsm);
    cudaFuncSetAttribute(gemm_out, cudaFuncAttributeMaxDynamicSharedMemorySize, gsm);

    // weights -> [hi | hi | lo]
    split3<<<EMB, 256>>>(Wq, w3p,                              2048, 1024);
    split3<<<EMB, 256>>>(Wk, w3p + (size_t)EMB * KSPLIT,       2048, 1024);
    split3<<<EMB, 256>>>(Wv, w3p + 2 * (size_t)EMB * KSPLIT,   2048, 1024);
    split3<<<EMB, 256>>>(Wo, w3p + 3 * (size_t)EMB * KSPLIT,   2048, 1024);

    // activations -> [hi|lo] (z-batched), then QKV projections (z-batched)
    split2<<<dim3(MTOT, 3), 256>>>(query, key, value, a2p);
    gemm_qkv<<<dim3(EMB / 128, MTOT / 128, 3), 256, gsm>>>(
        a2p, w3p, bq, bk, bv, q2p, k2p, vhp, vlp);

    // attention -> a2 slot 0 directly
    const int asmem = 98304;
    cudaFuncSetAttribute(attn_hmma, cudaFuncAttributeMaxDynamicSharedMemorySize, asmem);
    attn_hmma<<<dim3(SEQ / 128, NH, BATCH), 256, asmem>>>(q2p, k2p, vhp, vlp, a2p);

    // out projection -> d_out
    gemm_out<<<dim3(EMB / 128, MTOT / 128), 256, gsm>>>(
        a2p, w3p + 3 * (size_t)EMB * KSPLIT, bo, out);
}

// round 8
// speedup vs baseline: 3.3968x; 1.0061x over previous
#include <cuda_runtime.h>
#include <cuda_bf16.h>
#include <cstdint>
#include <cstddef>

#define BATCH 4
#define SEQ   2048
#define EMB   1024
#define NH    16
#define HD    64
#define MTOT  (BATCH * SEQ)        /* 8192 */
#define KSPLIT (3 * EMB)           /* 3072: W-side 3-block */
#define KA2   (2 * EMB)            /* 2048: A-side 2-block [hi|lo] */
#define BK    32
#define NITER (KSPLIT / BK)        /* 96 */
#define LOG2E 1.44269504f
#define NEG_BIG (-1e30f)
#define BHS   ((size_t)BATCH * NH * SEQ)   /* 131072 per-head rows */

// ---------------- scratch (__device__ globals; no allocs) -------------------
__device__ __align__(1024) __nv_bfloat16 g_a2[3][(size_t)MTOT * KA2];   // 3x32MB
__device__ __align__(1024) __nv_bfloat16 g_w3[4][(size_t)EMB * KSPLIT]; // 4x6MB
__device__ __align__(1024) __nv_bfloat16 g_q2[BHS * 128];  // [b,h,s][hi|lo] 32MB
__device__ __align__(1024) __nv_bfloat16 g_k2[BHS * 128];  // 32MB
__device__ __align__(1024) __nv_bfloat16 g_vh[BHS * HD];   // 16MB
__device__ __align__(1024) __nv_bfloat16 g_vl[BHS * HD];   // 16MB

// ---------------- PTX helpers (baseline ISA: sm_80-era ops) -----------------
__device__ __forceinline__ uint32_t smem_u32(const void* p) {
    uint32_t a;
    asm("{ .reg .u64 t; cvta.to.shared.u64 t, %1; cvt.u32.u64 %0, t; }" : "=r"(a) : "l"(p));
    return a;
}
#define CP_ASYNC16(dst, src) \
    asm volatile("cp.async.cg.shared.global [%0], [%1], 16;" :: "r"(dst), "l"(src) : "memory")
#define CP_COMMIT() asm volatile("cp.async.commit_group;" ::: "memory")
#define CP_WAIT1()  asm volatile("cp.async.wait_group 1;" ::: "memory")

__device__ __forceinline__ void ldsm4(uint32_t (&r)[4], uint32_t addr) {
    asm volatile("ldmatrix.sync.aligned.m8n8.x4.shared.b16 {%0,%1,%2,%3}, [%4];"
                 : "=r"(r[0]), "=r"(r[1]), "=r"(r[2]), "=r"(r[3]) : "r"(addr));
}
__device__ __forceinline__ void ldsm4t(uint32_t (&r)[4], uint32_t addr) {
    asm volatile("ldmatrix.sync.aligned.m8n8.x4.trans.shared.b16 {%0,%1,%2,%3}, [%4];"
                 : "=r"(r[0]), "=r"(r[1]), "=r"(r[2]), "=r"(r[3]) : "r"(addr));
}
__device__ __forceinline__ void mma16816(float (&d)[4], const uint32_t (&a)[4],
                                         uint32_t b0, uint32_t b1) {
    asm volatile(
        "mma.sync.aligned.m16n8k16.row.col.f32.bf16.bf16.f32 "
        "{%0,%1,%2,%3}, {%4,%5,%6,%7}, {%8,%9}, {%0,%1,%2,%3};"
        : "+f"(d[0]), "+f"(d[1]), "+f"(d[2]), "+f"(d[3])
        : "r"(a[0]), "r"(a[1]), "r"(a[2]), "r"(a[3]), "r"(b0), "r"(b1));
}
__device__ __forceinline__ uint32_t pk2(__nv_bfloat16 a, __nv_bfloat16 b) {
    __nv_bfloat162 t = __halves2bfloat162(a, b);
    return *reinterpret_cast<uint32_t*>(&t);
}
__device__ __forceinline__ void split1(float v, __nv_bfloat16& h, __nv_bfloat16& l) {
    h = __float2bfloat16(v);
    l = __float2bfloat16(v - __bfloat162float(h));
}

// ---------------------------------------------------------------------------
// split_all (one launch): z<4 -> weights [hi|hi|lo]; z>=4 -> activations [hi|lo]
// grid (1024, 7) x 256 threads.
// ---------------------------------------------------------------------------
__global__ __launch_bounds__(256)
void split_all(const float* __restrict__ q, const float* __restrict__ k,
               const float* __restrict__ v,
               const float* __restrict__ wq, const float* __restrict__ wk,
               const float* __restrict__ wv, const float* __restrict__ wo,
               __nv_bfloat16* __restrict__ a2, __nv_bfloat16* __restrict__ w3)
{
    const int z = blockIdx.y;
    if (z < 4) {
        const float* X = (z == 0) ? wq : (z == 1) ? wk : (z == 2) ? wv : wo;
        __nv_bfloat16* Y = w3 + (size_t)z * EMB * KSPLIT;
        size_t idx = (size_t)blockIdx.x * 256 + threadIdx.x;
        size_t row = idx >> 8;
        int    c   = (int)(idx & 255) << 2;
        float4 x = ((const float4*)X)[idx];
        __nv_bfloat16 h0, h1, h2, h3, l0, l1, l2, l3;
        split1(x.x, h0, l0); split1(x.y, h1, l1);
        split1(x.z, h2, l2); split1(x.w, h3, l3);
        uint2 hv = make_uint2(pk2(h0, h1), pk2(h2, h3));
        uint2 lv = make_uint2(pk2(l0, l1), pk2(l2, l3));
        size_t base = row * (size_t)KSPLIT + c;
        *(uint2*)(Y + base)        = hv;          // hi
        *(uint2*)(Y + base + 1024) = hv;          // hi (2nd block)
        *(uint2*)(Y + base + 2048) = lv;          // lo
    } else {
        const float* X = (z == 4) ? q : (z == 5) ? k : v;
        __nv_bfloat16* Y = a2 + (size_t)(z - 4) * MTOT * KA2;
        #pragma unroll
        for (int t = 0; t < 8; t++) {
            size_t idx = ((size_t)blockIdx.x * 8 + t) * 256 + threadIdx.x;
            size_t row = idx >> 8;
            int    c   = (int)(idx & 255) << 2;
            float4 x = ((const float4*)X)[idx];
            __nv_bfloat16 h0, h1, h2, h3, l0, l1, l2, l3;
            split1(x.x, h0, l0); split1(x.y, h1, l1);
            split1(x.z, h2, l2); split1(x.w, h3, l3);
            size_t base = row * (size_t)KA2 + c;
            *(uint2*)(Y + base)        = make_uint2(pk2(h0, h1), pk2(h2, h3));
            *(uint2*)(Y + base + 1024) = make_uint2(pk2(l0, l1), pk2(l2, l3));
        }
    }
}

// ---------------------------------------------------------------------------
// GEMM core: C = A2[*,2048(LUT->3072)] @ W3[*,3072]^T + bias
// 6-stage cp.async pipeline in pairs: ONE __syncthreads per 2 k-iters.
// mode 0: fp32 out; 1/2: per-head [hi|lo] (q2 scaled, k2); 3: vh/vl.
// ---------------------------------------------------------------------------
__device__ __forceinline__ int koffA(int it) { return (it < 64 ? it : it - 64) * BK; }

__device__ __forceinline__ void gemm_core(
    const __nv_bfloat16* __restrict__ A, const __nv_bfloat16* __restrict__ W,
    const float* __restrict__ bias, float* __restrict__ Cf,
    __nv_bfloat16* __restrict__ OH, __nv_bfloat16* __restrict__ OL,
    int mode, float scale, int m0, int n0, char* smem_raw)
{
    const uint32_t sbase = smem_u32(smem_raw);

    const int tid  = threadIdx.x;
    const int lane = tid & 31;
    const int wid  = tid >> 5;
    const int wm   = wid >> 2;
    const int wn   = wid & 3;

    const __nv_bfloat16* Ap = A + (size_t)m0 * KA2;
    const __nv_bfloat16* Wp = W + (size_t)n0 * KSPLIT;

    const int lrow = tid >> 2;
    const int lc   = tid & 3;

    const int arow  = wm * 64 + (lane & 15);
    const int akh   = lane >> 4;
    const int aswz  = (arow >> 1) & 3;
    const int brow  = wn * 32 + (lane & 7) + ((lane & 16) ? 8 : 0);
    const int bkh   = (lane >> 3) & 1;
    const int bswz  = (brow >> 1) & 3;

    float acc[4][4][4];
    #pragma unroll
    for (int i = 0; i < 4; i++)
        #pragma unroll
        for (int j = 0; j < 4; j++)
            #pragma unroll
            for (int k = 0; k < 4; k++) acc[i][j][k] = 0.f;

    // prologue: stages 0..3 (k-iters 0..3) as 2 groups of 2 stages
    #pragma unroll
    for (int s = 0; s < 4; s++) {
        uint32_t sA = sbase + s * 16384;
        uint32_t sB = sA + 8192;
        const __nv_bfloat16* ag = Ap + koffA(s) + lc * 8;
        const __nv_bfloat16* wg = Wp + (size_t)s * BK + lc * 8;
        #pragma unroll
        for (int h = 0; h < 2; h++) {
            int r  = lrow + h * 64;
            int cs = lc ^ ((r >> 1) & 3);
            CP_ASYNC16(sA + r * 64 + cs * 16, ag + (size_t)r * KA2);
            CP_ASYNC16(sB + r * 64 + cs * 16, wg + (size_t)r * KSPLIT);
        }
        if (s & 1) CP_COMMIT();
    }

    int st = 0;                       // stage of first k-iter in this superiter
    for (int j = 0; j < NITER / 2; j++) {
        CP_WAIT1();
        __syncthreads();

        #pragma unroll
        for (int half = 0; half < 2; half++) {
            const uint32_t sA = sbase + (st + half) * 16384;
            const uint32_t sB = sA + 8192;
            #pragma unroll
            for (int ks = 0; ks < 2; ks++) {
                uint32_t a[4][4];
                uint32_t b[4][2];
                const int ac = ((ks * 2 + akh) ^ aswz) * 16;
                const int bc = ((ks * 2 + bkh) ^ bswz) * 16;
                #pragma unroll
                for (int mi = 0; mi < 4; mi++)
                    ldsm4(a[mi], sA + (arow + mi * 16) * 64 + ac);
                #pragma unroll
                for (int nj = 0; nj < 2; nj++) {
                    uint32_t t4[4];
                    ldsm4(t4, sB + (brow + nj * 16) * 64 + bc);
                    b[nj * 2][0]     = t4[0]; b[nj * 2][1]     = t4[1];
                    b[nj * 2 + 1][0] = t4[2]; b[nj * 2 + 1][1] = t4[3];
                }
                #pragma unroll
                for (int mi = 0; mi < 4; mi++)
                    #pragma unroll
                    for (int ni = 0; ni < 4; ni++)
                        mma16816(acc[mi][ni], a[mi], b[ni][0], b[ni][1]);
            }
        }

        // prefetch pair for superiter j+2 (stages (st+4)%6, (st+5)%6);
        // that pair was read in superiter j-1 -> ordered by this superiter's sync.
        const int it0 = 2 * j + 4;
        if (it0 < NITER) {
            int pf = st + 4; if (pf >= 6) pf -= 6;
            #pragma unroll
            for (int half = 0; half < 2; half++) {
                const uint32_t dA = sbase + (pf + half) * 16384;
                const uint32_t dB = dA + 8192;
                const __nv_bfloat16* ag = Ap + koffA(it0 + half) + lc * 8;
                const __nv_bfloat16* wg = Wp + (size_t)(it0 + half) * BK + lc * 8;
                #pragma unroll
                for (int h = 0; h < 2; h++) {
                    int r  = lrow + h * 64;
                    int cs = lc ^ ((r >> 1) & 3);
                    CP_ASYNC16(dA + r * 64 + cs * 16, ag + (size_t)r * KA2);
                    CP_ASYNC16(dB + r * 64 + cs * 16, wg + (size_t)r * KSPLIT);
                }
            }
        }
        CP_COMMIT();
        st += 2; if (st >= 6) st -= 6;
    }

    // ---- epilogue ----
    const int trow = lane >> 2;
    const int tcol = (lane & 3) * 2;
    #pragma unroll
    for (int mi = 0; mi < 4; mi++) {
        const int row = m0 + wm * 64 + mi * 16 + trow;
        #pragma unroll
        for (int ni = 0; ni < 4; ni++) {
            const int col = n0 + wn * 32 + ni * 8 + tcol;
            const float b0 = __ldg(bias + col), b1 = __ldg(bias + col + 1);
            float v00 = acc[mi][ni][0] + b0, v01 = acc[mi][ni][1] + b1;
            float v10 = acc[mi][ni][2] + b0, v11 = acc[mi][ni][3] + b1;
            if (mode == 0) {
                *(float2*)(Cf + (size_t)row * EMB + col)       = make_float2(v00, v01);
                *(float2*)(Cf + (size_t)(row + 8) * EMB + col) = make_float2(v10, v11);
            } else {
                v00 *= scale; v01 *= scale; v10 *= scale; v11 *= scale;
                const int hh = col >> 6, d = col & 63;
                const size_t drow = ((size_t)((row >> 11) * NH + hh)) * SEQ + (row & 2047);
                __nv_bfloat16 h0, h1, h2, h3, l0, l1, l2, l3;
                split1(v00, h0, l0); split1(v01, h1, l1);
                split1(v10, h2, l2); split1(v11, h3, l3);
                if (mode == 3) {
                    *(uint32_t*)(OH + drow * HD + d)       = pk2(h0, h1);
                    *(uint32_t*)(OH + (drow + 8) * HD + d) = pk2(h2, h3);
                    *(uint32_t*)(OL + drow * HD + d)       = pk2(l0, l1);
                    *(uint32_t*)(OL + (drow + 8) * HD + d) = pk2(l2, l3);
                } else {
                    __nv_bfloat16* p0 = OH + drow * 128 + d;
                    __nv_bfloat16* p1 = OH + (drow + 8) * 128 + d;
                    *(uint32_t*)(p0)      = pk2(h0, h1);
                    *(uint32_t*)(p0 + 64) = pk2(l0, l1);
                    *(uint32_t*)(p1)      = pk2(h2, h3);
                    *(uint32_t*)(p1 + 64) = pk2(l2, l3);
                }
            }
        }
    }
}

// z-batched QKV projections: z=0 -> q2 (scaled), z=1 -> k2, z=2 -> vh/vl
__global__ __launch_bounds__(256, 2)
void gemm_qkv(const __nv_bfloat16* __restrict__ Abase,
              const __nv_bfloat16* __restrict__ Wbase,
              const float* __restrict__ bq, const float* __restrict__ bk,
              const float* __restrict__ bv,
              __nv_bfloat16* __restrict__ q2, __nv_bfloat16* __restrict__ k2,
              __nv_bfloat16* __restrict__ vh, __nv_bfloat16* __restrict__ vl)
{
    extern __shared__ __align__(1024) char smem_raw[];
    const int z = blockIdx.z;
    const __nv_bfloat16* A = Abase + (size_t)z * MTOT * KA2;
    const __nv_bfloat16* W = Wbase + (size_t)z * EMB * KSPLIT;
    const float* bias = (z == 0) ? bq : (z == 1) ? bk : bv;
    __nv_bfloat16* OH = (z == 0) ? q2 : (z == 1) ? k2 : vh;
    __nv_bfloat16* OL = (z == 2) ? vl : nullptr;
    const float scale = (z == 0) ? 0.125f : 1.0f;
    gemm_core(A, W, bias, nullptr, OH, OL, z + 1, scale,
              blockIdx.y * 128, blockIdx.x * 128, smem_raw);
}

// out projection -> fp32 d_out
__global__ __launch_bounds__(256, 2)
void gemm_out(const __nv_bfloat16* __restrict__ A, const __nv_bfloat16* __restrict__ W,
              const float* __restrict__ bias, float* __restrict__ Cf)
{
    extern __shared__ __align__(1024) char smem_raw[];
    gemm_core(A, W, bias, Cf, nullptr, nullptr, 0, 1.0f,
              blockIdx.y * 128, blockIdx.x * 128, smem_raw);
}

// ---------------------------------------------------------------------------
// HMMA flash attention (causal), bf16 3-term via 2-block [hi|lo] operands.
// Block: 128 queries x 1 head, 8 warps, 64-key tiles, double-buffered.
// LPT: heaviest blocks (largest bx) launch first via reversed blockIdx.x.
// ---------------------------------------------------------------------------
__global__ __launch_bounds__(256, 2)
void attn_hmma(const __nv_bfloat16* __restrict__ Q2, const __nv_bfloat16* __restrict__ K2,
               const __nv_bfloat16* __restrict__ VH, const __nv_bfloat16* __restrict__ VL,
               __nv_bfloat16* __restrict__ A2)
{
    extern __shared__ __align__(1024) char smr[];
    const uint32_t sb = smem_u32(smr);
    const uint32_t QS = sb;                 // 4 slabs * 8192B
    const uint32_t KS = sb + 32768;         // 2 stages * 16384
    const uint32_t VS = sb + 65536;         // 2 stages * 16384

    const int tid  = threadIdx.x;
    const int lane = tid & 31;
    const int wid  = tid >> 5;
    const int bx   = gridDim.x - 1 - blockIdx.x;   // LPT: heavy first
    const int head = blockIdx.y;
    const int bz   = blockIdx.z;
    const int qb0  = bx * 128;
    const size_t bh = (size_t)(bz * NH + head);
    const int nkb  = 2 * bx + 2;

    const __nv_bfloat16* Qp = Q2 + (bh * SEQ + qb0) * 128;
    const __nv_bfloat16* Kp = K2 + bh * SEQ * 128;
    const __nv_bfloat16* VHp = VH + bh * SEQ * HD;
    const __nv_bfloat16* VLp = VL + bh * SEQ * HD;

    {
        const int r1 = tid >> 2, lc = tid & 3;
        #pragma unroll
        for (int kc = 0; kc < 4; kc++)
            #pragma unroll
            for (int h = 0; h < 2; h++) {
                int r = r1 + h * 64;
                int cs = lc ^ ((r >> 1) & 3);
                CP_ASYNC16(QS + kc * 8192 + r * 64 + cs * 16,
                           Qp + (size_t)r * 128 + kc * 32 + lc * 8);
            }
        int cs = lc ^ ((r1 >> 1) & 3);
        #pragma unroll
        for (int kc = 0; kc < 4; kc++)
            CP_ASYNC16(KS + kc * 4096 + r1 * 64 + cs * 16,
                       Kp + (size_t)r1 * 128 + kc * 32 + lc * 8);
        const int vr = tid >> 3, vc = tid & 7;
        #pragma unroll
        for (int h = 0; h < 2; h++) {
            int r = vr + h * 32;
            int pc = vc ^ (r & 7);
            CP_ASYNC16(VS + r * 128 + pc * 16, VHp + (size_t)r * HD + vc * 8);
            CP_ASYNC16(VS + 8192 + r * 128 + pc * 16, VLp + (size_t)r * HD + vc * 8);
        }
        CP_COMMIT();
    }

    const int arow = wid * 16 + (lane & 15);
    const int akh  = lane >> 4;
    const int aswz = (arow >> 1) & 3;
    const int brow = (lane & 7) + ((lane & 16) ? 8 : 0);
    const int bkh  = (lane >> 3) & 1;
    const int bswz = (brow >> 1) & 3;
    const int vrow = (lane & 7) + 8 * ((lane >> 3) & 1);
    const int vchb = lane >> 4;
    const int vswz = lane & 7;

    float of[8][4];
    #pragma unroll
    for (int i = 0; i < 8; i++)
        #pragma unroll
        for (int j = 0; j < 4; j++) of[i][j] = 0.f;
    float mq[2] = { NEG_BIG, NEG_BIG };
    float lq[2] = { 0.f, 0.f };

    const int qrow0 = qb0 + wid * 16 + (lane >> 2);

    for (int kb = 0; kb < nkb; kb++) {
        const int st = kb & 1;
        const int kbase = kb * 64;

        if (kb + 1 < nkb) {
            const int nb = (kb + 1) * 64;
            const int s2 = st ^ 1;
            const int r1 = tid >> 2, lc = tid & 3;
            int cs = lc ^ ((r1 >> 1) & 3);
            #pragma unroll
            for (int kc = 0; kc < 4; kc++)
                CP_ASYNC16(KS + s2 * 16384 + kc * 4096 + r1 * 64 + cs * 16,
                           Kp + (size_t)(nb + r1) * 128 + kc * 32 + lc * 8);
            const int vr = tid >> 3, vc = tid & 7;
            #pragma unroll
            for (int h = 0; h < 2; h++) {
                int r = vr + h * 32;
                int pc = vc ^ (r & 7);
                CP_ASYNC16(VS + s2 * 16384 + r * 128 + pc * 16,
                           VHp + (size_t)(nb + r) * HD + vc * 8);
                CP_ASYNC16(VS + s2 * 16384 + 8192 + r * 128 + pc * 16,
                           VLp + (size_t)(nb + r) * HD + vc * 8);
            }
        }
        CP_COMMIT();
        CP_WAIT1();
        __syncthreads();

        float sf[8][4];
        #pragma unroll
        for (int i = 0; i < 8; i++)
            #pragma unroll
            for (int j = 0; j < 4; j++) sf[i][j] = 0.f;

        const uint32_t Kst = KS + st * 16384;
        const int qsel[6] = { 0, 1, 2, 3, 0, 1 };
        const int ksel[6] = { 0, 1, 0, 1, 2, 3 };
        #pragma unroll
        for (int t = 0; t < 6; t++) {
            #pragma unroll
            for (int ks = 0; ks < 2; ks++) {
                uint32_t a[4];
                ldsm4(a, QS + qsel[t] * 8192 + arow * 64 + (((ks * 2 + akh) ^ aswz) * 16));
                const int bc = ((ks * 2 + bkh) ^ bswz) * 16;
                #pragma unroll
                for (int np = 0; np < 4; np++) {
                    uint32_t t4[4];
                    ldsm4(t4, Kst + ksel[t] * 4096 + (np * 16 + brow) * 64 + bc);
                    mma16816(sf[2 * np],     a, t4[0], t4[1]);
                    mma16816(sf[2 * np + 1], a, t4[2], t4[3]);
                }
            }
        }

        if (kb >= nkb - 2) {
            #pragma unroll
            for (int nt = 0; nt < 8; nt++) {
                int col = kbase + nt * 8 + 2 * (lane & 3);
                if (col     > qrow0)     sf[nt][0] = NEG_BIG;
                if (col + 1 > qrow0)     sf[nt][1] = NEG_BIG;
                if (col     > qrow0 + 8) sf[nt][2] = NEG_BIG;
                if (col + 1 > qrow0 + 8) sf[nt][3] = NEG_BIG;
            }
        }

        #pragma unroll
        for (int h = 0; h < 2; h++) {
            float mloc = NEG_BIG;
            #pragma unroll
            for (int nt = 0; nt < 8; nt++)
                mloc = fmaxf(mloc, fmaxf(sf[nt][2 * h], sf[nt][2 * h + 1]));
            mloc = fmaxf(mloc, __shfl_xor_sync(0xffffffffu, mloc, 1));
            mloc = fmaxf(mloc, __shfl_xor_sync(0xffffffffu, mloc, 2));
            float mnew = fmaxf(mq[h], mloc);
            float corr = exp2f((mq[h] - mnew) * LOG2E);
            mq[h] = mnew;
            lq[h] *= corr;
            float ps = 0.f;
            #pragma unroll
            for (int nt = 0; nt < 8; nt++) {
                float p0 = exp2f((sf[nt][2 * h] - mnew) * LOG2E);
                float p1 = exp2f((sf[nt][2 * h + 1] - mnew) * LOG2E);
                sf[nt][2 * h] = p0; sf[nt][2 * h + 1] = p1;
                ps += p0 + p1;
                of[nt][2 * h] *= corr; of[nt][2 * h + 1] *= corr;
            }
            ps += __shfl_xor_sync(0xffffffffu, ps, 1);
            ps += __shfl_xor_sync(0xffffffffu, ps, 2);
            lq[h] += ps;
        }

        const uint32_t Vst = VS + st * 16384;
        #pragma unroll
        for (int kc2 = 0; kc2 < 4; kc2++) {
            const int j0 = 2 * kc2, j1 = j0 + 1;
            uint32_t ph[4], pl[4];
            #pragma unroll
            for (int q = 0; q < 4; q++) {
                const float p0 = (q & 2) ? sf[j1][(q & 1) * 2]     : sf[j0][(q & 1) * 2];
                const float p1 = (q & 2) ? sf[j1][(q & 1) * 2 + 1] : sf[j0][(q & 1) * 2 + 1];
                __nv_bfloat16 h0, h1, l0, l1;
                split1(p0, h0, l0); split1(p1, h1, l1);
                ph[q] = pk2(h0, h1);
                pl[q] = pk2(l0, l1);
            }
            const uint32_t rowoff = (kc2 * 16 + vrow) * 128;
            #pragma unroll
            for (int np = 0; np < 4; np++) {
                const int pc = (2 * np + vchb) ^ vswz;
                uint32_t bh4[4], bl4[4];
                ldsm4t(bh4, Vst + rowoff + pc * 16);
                ldsm4t(bl4, Vst + 8192 + rowoff + pc * 16);
                mma16816(of[2 * np],     ph, bh4[0], bh4[1]);
                mma16816(of[2 * np + 1], ph, bh4[2], bh4[3]);
                mma16816(of[2 * np],     pl, bh4[0], bh4[1]);
                mma16816(of[2 * np + 1], pl, bh4[2], bh4[3]);
                mma16816(of[2 * np],     ph, bl4[0], bl4[1]);
                mma16816(of[2 * np + 1], ph, bl4[2], bl4[3]);
            }
        }
        __syncthreads();
    }

    const float inv0 = 1.f / lq[0];
    const float inv1 = 1.f / lq[1];
    const size_t ar0 = (size_t)bz * SEQ + qb0 + wid * 16 + (lane >> 2);
    const size_t ar1 = ar0 + 8;
    const int colb = head * 64 + 2 * (lane & 3);
    #pragma unroll
    for (int nt = 0; nt < 8; nt++) {
        int col = colb + nt * 8;
        float v0 = of[nt][0] * inv0, v1 = of[nt][1] * inv0;
        float v2 = of[nt][2] * inv1, v3 = of[nt][3] * inv1;
        __nv_bfloat16 h0, h1, h2, h3, l0, l1, l2, l3;
        split1(v0, h0, l0); split1(v1, h1, l1);
        split1(v2, h2, l2); split1(v3, h3, l3);
        __nv_bfloat16* d0 = A2 + ar0 * KA2 + col;
        __nv_bfloat16* d1 = A2 + ar1 * KA2 + col;
        *(uint32_t*)(d0)        = pk2(h0, h1);
        *(uint32_t*)(d0 + 1024) = pk2(l0, l1);
        *(uint32_t*)(d1)        = pk2(h2, h3);
        *(uint32_t*)(d1 + 1024) = pk2(l2, l3);
    }
}

// ---------------------------------------------------------------------------
extern "C" void kernel_launch(void* const* d_in, const int* in_sizes, int n_in,
                              void* d_out, int out_size)
{
    const float* query = (const float*)d_in[0];
    const float* key   = (const float*)d_in[1];
    const float* value = (const float*)d_in[2];
    const float* Wq = (const float*)d_in[4];  const float* bq = (const float*)d_in[5];
    const float* Wk = (const float*)d_in[6];  const float* bk = (const float*)d_in[7];
    const float* Wv = (const float*)d_in[8];  const float* bv = (const float*)d_in[9];
    const float* Wo = (const float*)d_in[10]; const float* bo = (const float*)d_in[11];
    float* out = (float*)d_out;

    __nv_bfloat16 *a2p, *w3p, *q2p, *k2p, *vhp, *vlp;
    cudaGetSymbolAddress((void**)&a2p, g_a2);
    cudaGetSymbolAddress((void**)&w3p, g_w3);
    cudaGetSymbolAddress((void**)&q2p, g_q2);
    cudaGetSymbolAddress((void**)&k2p, g_k2);
    cudaGetSymbolAddress((void**)&vhp, g_vh);
    cudaGetSymbolAddress((void**)&vlp, g_vl);

    const int gsm = 6 * 16384;   // 96KB dynamic (6-stage pipeline)
    cudaFuncSetAttribute(gemm_qkv, cudaFuncAttributeMaxDynamicSharedMemorySize, gsm);
    cudaFuncSetAttribute(gemm_out, cudaFuncAttributeMaxDynamicSharedMemorySize, gsm);

    // all splits (4 weights + 3 activations) in one launch
    split_all<<<dim3(1024, 7), 256>>>(query, key, value, Wq, Wk, Wv, Wo, a2p, w3p);

    // QKV projections (z-batched) with fused per-head split epilogues
    gemm_qkv<<<dim3(EMB / 128, MTOT / 128, 3), 256, gsm>>>(
        a2p, w3p, bq, bk, bv, q2p, k2p, vhp, vlp);

    // attention -> a2 slot 0 directly
    const int asmem = 98304;
    cudaFuncSetAttribute(attn_hmma, cudaFuncAttributeMaxDynamicSharedMemorySize, asmem);
    attn_hmma<<<dim3(SEQ / 128, NH, BATCH), 256, asmem>>>(q2p, k2p, vhp, vlp, a2p);

    // out projection -> d_out
    gemm_out<<<dim3(EMB / 128, MTOT / 128), 256, gsm>>>(
        a2p, w3p + 3 * (size_t)EMB * KSPLIT, bo, out);
}